// round 15
// baseline (speedup 1.0000x reference)
#include <cuda_runtime.h>
#include <cuda_bf16.h>
#include <cuda_fp8.h>
#include <math.h>

#define BB 6
#define HH 320
#define WW 320
#define NP (HH*WW)
#define BNP (BB*NP)
#define NN 1024
#define DD 128
#define NCR 500
#define CAND_MAX 2048
#define CELLS 20
#define NCH 32
#define CHSZ 32

// ---------------- scratch (no allocation allowed) ----------------
__device__ float d_target[BNP];
__device__ int   d_cand_cnt[BB];
__device__ unsigned long long d_cand[BB*CAND_MAX];
__device__ float d_tkval[BB*NCR];
__device__ int   d_tkidx[BB*NCR];

__device__ float4 d_pt[BB*NN];              // (sx, sy, 0.5*x2, -)
__device__ float4 d_nd[BB*BB*NN];           // (dx, dy, 0.5-0.5*y2, -)
__device__ unsigned char d_vis[BB*BB*NN];
__device__ unsigned char d_desc8[BB*NN*DD]; // pre-normalized e4m3 (distinction GEMM)
__device__ float d_descn[BB*NN*DD];         // pre-normalized fp32
__device__ float d_S[BB*NN*DD];             // suffix sums of d_descn over n>m

__device__ float d_M[BB*BB][9];             // K Ri^T Rj Kinv
__device__ float d_V[BB*BB][3];             // K Ri^T (tj - ti)

__device__ int d_cellstart[BB][CELLS*CELLS+1];
__device__ int d_cellidx[BB][NN];

__device__ double d_acc[8];                 // 0 dsum,1 psum,3 vsum,5 bce,6 reg
__device__ unsigned long long d_cnt[2];     // 0 pos count, 1 total vis&triu count
__device__ float d_gw[7];

__device__ __forceinline__ int reflecti(int i, int n){ if (i < 0) i = -i; if (i >= n) i = 2*n-2-i; return i; }
__device__ __forceinline__ int clampi(int i, int n){ return min(max(i,0), n-1); }

// ---------------- tiny init ----------------
__global__ void k_init0() {
    int t = threadIdx.x;
    if (t < 8) d_acc[t] = 0.0;
    if (t < 2) d_cnt[t] = 0ULL;
    if (t < BB) d_cand_cnt[t] = 0;
    if (t == 0) {
        float g[7]; float s = 0.f;
        for (int i = 0; i < 7; i++) { float ax = (float)i - 3.0f; g[i] = expf(-0.5f*ax*ax); s += g[i]; }
        for (int i = 0; i < 7; i++) d_gw[i] = g[i] / s;
    }
}

// ---------------- precompute composed projection transforms (36 pairs) ----------------
__global__ void k_xform(const float* __restrict__ poses, const float* __restrict__ Km) {
    int t = threadIdx.x;
    if (t >= BB*BB) return;
    int i = t / BB, j = t % BB;
    float a00=Km[0],a01=Km[1],a02=Km[2],a10=Km[3],a11=Km[4],a12=Km[5],a20=Km[6],a21=Km[7],a22=Km[8];
    // Kinv via cofactors
    float c00 = a11*a22-a12*a21, c01 = a02*a21-a01*a22, c02 = a01*a12-a02*a11;
    float c10 = a12*a20-a10*a22, c11 = a00*a22-a02*a20, c12 = a02*a10-a00*a12;
    float c20 = a10*a21-a11*a20, c21 = a01*a20-a00*a21, c22 = a00*a11-a01*a10;
    float det = a00*c00 + a01*c10 + a02*c20;
    float id = 1.0f/det;
    float KI[9] = { c00*id, c01*id, c02*id, c10*id, c11*id, c12*id, c20*id, c21*id, c22*id };
    float K[9]  = { a00,a01,a02, a10,a11,a12, a20,a21,a22 };
    const float* Pi = poses + i*16;
    const float* Pj = poses + j*16;
    // A = Ri^T  (A[r][c] = Ri[c][r] = Pi[c*4+r]) ; B = Rj
    float A[9], Bm[9];
    for (int r = 0; r < 3; r++)
        for (int c = 0; c < 3; c++) {
            A[r*3+c]  = Pi[c*4+r];
            Bm[r*3+c] = Pj[r*4+c];
        }
    float T1[9], T2[9], M[9];
    for (int r = 0; r < 3; r++)           // T1 = K*A
        for (int c = 0; c < 3; c++)
            T1[r*3+c] = K[r*3+0]*A[c] + K[r*3+1]*A[3+c] + K[r*3+2]*A[6+c];
    for (int r = 0; r < 3; r++)           // T2 = T1*B
        for (int c = 0; c < 3; c++)
            T2[r*3+c] = T1[r*3+0]*Bm[c] + T1[r*3+1]*Bm[3+c] + T1[r*3+2]*Bm[6+c];
    for (int r = 0; r < 3; r++)           // M = T2*Kinv
        for (int c = 0; c < 3; c++)
            M[r*3+c] = T2[r*3+0]*KI[c] + T2[r*3+1]*KI[3+c] + T2[r*3+2]*KI[6+c];
    float dt[3] = { Pj[3]-Pi[3], Pj[7]-Pi[7], Pj[11]-Pi[11] };
    for (int r = 0; r < 9; r++) d_M[t][r] = M[r];
    for (int r = 0; r < 3; r++)
        d_V[t][r] = T1[r*3+0]*dt[0] + T1[r*3+1]*dt[1] + T1[r*3+2]*dt[2];
}

// ---------------- fully-fused gray+sobel+gaussian+GFTT+NMS+blockmax+emit ----------------
__global__ __launch_bounds__(512) void k_front(const float* __restrict__ imgs) {
    extern __shared__ float buf[];
    float* gr = buf;               // 44x44
    float* p0 = buf + 1936;        // 42x42
    float* p1 = p0 + 1764;
    float* p2 = p1 + 1764;
    float* h0 = buf + 7228;        // 42x36
    float* h1 = h0 + 1512;
    float* h2 = h1 + 1512;
    float* rs = buf;               // 36x36 overlays gr
    float* hm = buf + 1936;        // 36x32 overlays p0

    int b = blockIdx.z; int y0 = blockIdx.y*32, x0 = blockIdx.x*32;
    int tid = threadIdx.x;
    const float* base = imgs + (size_t)b*3*NP;

    for (int l = tid; l < 44*44; l += 512) {
        int r = l/44, c = l%44;
        int gy = clampi(y0 + r - 6, HH), gx = clampi(x0 + c - 6, WW);
        int p = gy*WW + gx;
        gr[l] = 0.299f*base[p] + 0.587f*base[NP + p] + 0.114f*base[2*NP + p];
    }
    __syncthreads();

    for (int l = tid; l < 42*42; l += 512) {
        int r = l/42, c = l%42;
        int py = y0 + r - 5, px = x0 + c - 5;
        int ry = reflecti(py, HH), rx = reflecti(px, WW);
        #define GS(yy,xx) gr[(clampi((yy),HH) - (y0-6))*44 + (clampi((xx),WW) - (x0-6))]
        float a00=GS(ry-1,rx-1), a01=GS(ry-1,rx), a02=GS(ry-1,rx+1);
        float a10=GS(ry,  rx-1),                  a12=GS(ry,  rx+1);
        float a20=GS(ry+1,rx-1), a21=GS(ry+1,rx), a22=GS(ry+1,rx+1);
        #undef GS
        float gxv = 0.125f*(a02-a00) + 0.25f*(a12-a10) + 0.125f*(a22-a20);
        float gyv = 0.125f*(a20-a00) + 0.25f*(a21-a01) + 0.125f*(a22-a02);
        p0[l] = gxv*gxv; p1[l] = gyv*gyv; p2[l] = gxv*gyv;
    }
    __syncthreads();

    for (int l = tid; l < 42*36; l += 512) {
        int r = l/36, c = l%36;
        float s0=0.f, s1=0.f, s2=0.f;
        #pragma unroll
        for (int d = 0; d < 7; d++) {
            float w = d_gw[d];
            int q = r*42 + c + d;
            s0 += w*p0[q]; s1 += w*p1[q]; s2 += w*p2[q];
        }
        h0[l]=s0; h1[l]=s1; h2[l]=s2;
    }
    __syncthreads();

    for (int l = tid; l < 36*36; l += 512) {
        int rr = l/36, c = l%36;
        float s0=0.f, s1=0.f, s2=0.f;
        #pragma unroll
        for (int d = 0; d < 7; d++) {
            float w = d_gw[d];
            int q = (rr + d)*36 + c;
            s0 += w*h0[q]; s1 += w*h1[q]; s2 += w*h2[q];
        }
        float tr = s0 + s1, df = s0 - s1;
        float disc = sqrtf(fmaxf(df*df + 4.0f*s2*s2, 0.f));
        float v = 0.5f*(tr - disc);
        int gy = y0 + rr - 2, gx = x0 + c - 2;
        rs[l] = (gy>=0 && gy<HH && gx>=0 && gx<WW) ? v : -INFINITY;
    }
    __syncthreads();

    for (int l = tid; l < 36*32; l += 512) {
        int r = l >> 5, c = l & 31;
        float m = -INFINITY;
        #pragma unroll
        for (int dx = 0; dx < 5; dx++) m = fmaxf(m, rs[r*36 + c + dx]);
        hm[l] = m;
    }
    __syncthreads();

    int lane = tid & 31, w = tid >> 5;
    int br = w >> 2, bc = w & 3;
    float nv[2];
    #pragma unroll
    for (int s = 0; s < 2; s++) {
        int p = lane + s*32;
        int yy = br*8 + (p >> 3), xx = bc*8 + (p & 7);
        float v = rs[(yy+2)*36 + xx + 2];
        float m = -INFINITY;
        #pragma unroll
        for (int dy = 0; dy < 5; dy++) m = fmaxf(m, hm[(yy+dy)*32 + xx]);
        nv[s] = (v == m) ? v : 0.f;
    }
    float bm = fmaxf(nv[0], nv[1]);
    #pragma unroll
    for (int o = 16; o > 0; o >>= 1) bm = fmaxf(bm, __shfl_xor_sync(~0u, bm, o));
    if (bm > 0.f) {
        #pragma unroll
        for (int s = 0; s < 2; s++) {
            if (nv[s] == bm) {
                int p = lane + s*32;
                int gy = y0 + br*8 + (p >> 3), gx = x0 + bc*8 + (p & 7);
                unsigned p_idx = (unsigned)(gy*WW + gx);
                int pos = atomicAdd(&d_cand_cnt[b], 1);
                if (pos < CAND_MAX)
                    d_cand[b*CAND_MAX + pos] =
                        ((unsigned long long)__float_as_uint(bm) << 32) | (unsigned)(~p_idx);
            }
        }
    }
}

// ---------------- per-image bitonic sort + top-500 ----------------
__global__ void k_sort(void) {
    __shared__ unsigned long long s[CAND_MAX];
    int b = blockIdx.x;
    int cnt = min(d_cand_cnt[b], CAND_MAX);
    for (int p = threadIdx.x; p < CAND_MAX; p += blockDim.x)
        s[p] = (p < cnt) ? d_cand[b*CAND_MAX + p] : 0ULL;
    __syncthreads();
    for (int k = 2; k <= CAND_MAX; k <<= 1) {
        for (int j = k >> 1; j > 0; j >>= 1) {
            for (int p = threadIdx.x; p < CAND_MAX; p += blockDim.x) {
                int q = p ^ j;
                if (q > p) {
                    unsigned long long va = s[p], vb = s[q];
                    bool asc = ((p & k) == 0);
                    if ((va < vb) == asc) { s[p] = vb; s[q] = va; }
                }
            }
            __syncthreads();
        }
    }
    for (int p = threadIdx.x; p < NCR; p += blockDim.x) {
        unsigned long long key = s[p];
        float val; int idx;
        if (key == 0ULL) { val = 0.f; idx = 0; }
        else { val = __uint_as_float((unsigned)(key >> 32)); idx = (int)(~(unsigned)key); }
        d_tkval[b*NCR + p] = val;
        d_tkidx[b*NCR + p] = idx;
    }
}

// ---------------- full projection helper (used by scatter only) ----------------
__device__ __forceinline__ void project_pt(
    const float* __restrict__ depths, const float* __restrict__ poses, const float* __restrict__ Km,
    int j, int i, float pxx, float pxy, float& u, float& v, float& z)
{
    int xi = (int)fminf(fmaxf(rintf(pxx), 0.f), (float)(WW-1));
    int yi = (int)fminf(fmaxf(rintf(pxy), 0.f), (float)(HH-1));
    float dep = depths[(j*HH + yi)*WW + xi];
    const float* M = d_M[i*BB + j];
    const float* V = d_V[i*BB + j];
    float q0 = M[0]*pxx + M[1]*pxy + M[2];
    float q1 = M[3]*pxx + M[4]*pxy + M[5];
    float q2 = M[6]*pxx + M[7]*pxy + M[8];
    float uu = fmaf(q0, dep, V[0]);
    float vv = fmaf(q1, dep, V[1]);
    float ww = fmaf(q2, dep, V[2]);
    z = ww;
    float zs = (fabsf(ww) > 1e-6f) ? ww : 1e-6f;
    u = uu/zs; v = vv/zs;
}

// ---------------- corner project + scatter-max ----------------
__global__ void k_scatter(const float* __restrict__ depths, const float* __restrict__ poses,
                          const float* __restrict__ Km) {
    int t = blockIdx.x*blockDim.x + threadIdx.x;
    if (t >= BB*BB*NCR) return;
    int i = t / (BB*NCR);
    int r = t % (BB*NCR);
    int j = r / NCR, n = r % NCR;
    float val = d_tkval[i*NCR + n];
    if (val <= 0.f) return;
    int idx = d_tkidx[j*NCR + n];
    float cx = (float)(idx % WW), cy = (float)(idx / WW);
    float pnx = cx*2.0f/(float)(WW-1) - 1.0f;
    float pny = cy*2.0f/(float)(HH-1) - 1.0f;
    float pxx = (pnx + 1.0f)*(float)(WW-1)*0.5f;
    float pxy = (pny + 1.0f)*(float)(HH-1)*0.5f;
    float u, v, z;
    project_pt(depths, poses, Km, j, i, pxx, pxy, u, v, z);
    bool vis = (z > 0.1f) && (u >= 0.f) && (u <= (float)(WW-1)) && (v >= 0.f) && (v <= (float)(HH-1));
    if (!vis) return;
    float un = u*2.0f/(float)(WW-1) - 1.0f;
    float vn = v*2.0f/(float)(HH-1) - 1.0f;
    float dxp = rintf((un + 1.0f)*(float)(WW-1)*0.5f);
    float dyp = rintf((vn + 1.0f)*(float)(HH-1)*0.5f);
    int ix = (int)dxp, iy = (int)dyp;
    if (dxp >= 0.f && dyp >= 0.f && ix < WW && iy < HH)
        atomicMax((int*)&d_target[j*NP + iy*WW + ix], __float_as_int(val));
}

// ---------------- tiled target NMS + BCE + laplacian reg ----------------
__global__ __launch_bounds__(512) void k_score(const float* __restrict__ scores) {
    __shared__ float tg[36][36], sc[36][36];
    __shared__ float rsum[36][32], rmax[36][32];
    __shared__ float wsum[16][2];
    int b = blockIdx.z; int y0 = blockIdx.y*32, x0 = blockIdx.x*32;
    int tid = threadIdx.x; int lane = tid & 31, w = tid >> 5;
    for (int l = tid; l < 36*36; l += 512) {
        int r = l/36, c = l%36;
        int gy = y0 + r - 2, gx = x0 + c - 2;
        tg[r][c] = (gy>=0 && gy<HH && gx>=0 && gx<WW) ? d_target[b*NP + gy*WW + gx] : -INFINITY;
        int ry = reflecti(gy, HH), rx = reflecti(gx, WW);
        sc[r][c] = scores[b*NP + ry*WW + rx];
    }
    __syncthreads();
    for (int l = tid; l < 36*32; l += 512) {
        int r = l >> 5, c = l & 31;
        float s = 0.f, m = -INFINITY;
        #pragma unroll
        for (int dx = 0; dx < 5; dx++) {
            s += sc[r][c+dx];
            m = fmaxf(m, tg[r][c+dx]);
        }
        rsum[r][c] = s; rmax[r][c] = m;
    }
    __syncthreads();
    int tx = tid & 31, ty0 = tid >> 5;
    float bce = 0.f, reg = 0.f;
    #pragma unroll
    for (int s = 0; s < 2; s++) {
        int r = ty0 + s*16;
        float tv = tg[r+2][tx+2];
        float m = -INFINITY, ssum = 0.f;
        #pragma unroll
        for (int dy = 0; dy < 5; dy++) {
            ssum += rsum[r+dy][tx];
            m = fmaxf(m, rmax[r+dy][tx]);
        }
        bool tb = (tv > 0.f) && (tv == m);
        float sv = sc[r+2][tx+2];
        float pcv = fminf(fmaxf(sv, 1e-12f), 1.0f - 1e-12f);
        bce += -(tb ? logf(pcv) : logf(1.0f - pcv));
        float lap = (ssum - sv)*(1.0f/48.0f) - 0.5f*sv;
        reg += sv*expf(-lap);
    }
    #pragma unroll
    for (int o = 16; o > 0; o >>= 1) {
        bce += __shfl_xor_sync(~0u, bce, o);
        reg += __shfl_xor_sync(~0u, reg, o);
    }
    if (lane == 0) { wsum[w][0] = bce; wsum[w][1] = reg; }
    __syncthreads();
    if (w == 0) {
        float t0 = (lane < 16) ? wsum[lane][0] : 0.f;
        float t1 = (lane < 16) ? wsum[lane][1] : 0.f;
        #pragma unroll
        for (int o = 8; o > 0; o >>= 1) {
            t0 += __shfl_xor_sync(~0u, t0, o);
            t1 += __shfl_xor_sync(~0u, t1, o);
        }
        if (lane == 0) { atomicAdd(&d_acc[5], (double)t0); atomicAdd(&d_acc[6], (double)t1); }
    }
}

// ---------------- per-point prep ----------------
__global__ void k_prep(const float* __restrict__ points, const float* __restrict__ desc) {
    int idx = blockIdx.x*blockDim.x + threadIdx.x;
    if (idx >= BB*NN) return;
    float pnx = points[idx*2], pny = points[idx*2+1];
    float sx = (pnx + 1.0f)*(float)(WW-1)*0.5f;
    float sy = (pny + 1.0f)*(float)(HH-1)*0.5f;
    d_pt[idx] = make_float4(sx, sy, 0.5f*(sx*sx + sy*sy), 0.f);
    const float4* dv = (const float4*)(desc + (size_t)idx*DD);
    float xx = 0.f;
    #pragma unroll
    for (int c = 0; c < 32; c++) {
        float4 v = dv[c];
        xx += v.x*v.x + v.y*v.y + v.z*v.z + v.w*v.w;
    }
    float inv = rsqrtf(fmaxf(xx, 1e-30f));
    float4* on = (float4*)(d_descn + (size_t)idx*DD);
    uint4* ob = (uint4*)(d_desc8 + (size_t)idx*DD);
    #pragma unroll
    for (int c = 0; c < 8; c++) {
        union { unsigned char b[16]; uint4 u; } pk;
        #pragma unroll
        for (int g = 0; g < 4; g++) {
            float4 v = dv[c*4 + g];
            float4 nvv = make_float4(v.x*inv, v.y*inv, v.z*inv, v.w*inv);
            on[c*4 + g] = nvv;
            pk.b[g*4+0] = __nv_fp8_e4m3(nvv.x).__x;
            pk.b[g*4+1] = __nv_fp8_e4m3(nvv.y).__x;
            pk.b[g*4+2] = __nv_fp8_e4m3(nvv.z).__x;
            pk.b[g*4+3] = __nv_fp8_e4m3(nvv.w).__x;
        }
        ob[c] = pk.u;
    }
}

// ---------------- fused parallel suffix scan ----------------
__global__ __launch_bounds__(1024) void k_scan() {
    __shared__ float cs[NCH][33];
    int b = blockIdx.x, dg = blockIdx.y;
    int tid = threadIdx.x;
    int c = tid >> 5, dl = tid & 31;
    int d = dg*32 + dl;
    const float* dn = d_descn + (size_t)b*NN*DD;
    float* S = d_S + (size_t)b*NN*DD;
    float s = 0.f;
    #pragma unroll 8
    for (int n = c*CHSZ; n < c*CHSZ + CHSZ; n++) s += dn[n*DD + d];
    cs[c][dl] = s;
    __syncthreads();
    float run = 0.f;
    for (int cc = c+1; cc < NCH; cc++) run += cs[cc][dl];
    for (int n = c*CHSZ + CHSZ - 1; n >= c*CHSZ; n--) {
        S[n*DD + d] = run;
        run += dn[n*DD + d];
    }
}

// ---------------- spatial grid over src positions per image ----------------
__global__ __launch_bounds__(512) void k_cells() {
    __shared__ int cnt[CELLS*CELLS];
    __shared__ int start[CELLS*CELLS+1];
    __shared__ int cur[CELLS*CELLS];
    int b = blockIdx.x, tid = threadIdx.x;
    for (int i = tid; i < CELLS*CELLS; i += 512) cnt[i] = 0;
    __syncthreads();
    for (int m = tid; m < NN; m += 512) {
        float4 pt = d_pt[b*NN+m];
        int xi = min(CELLS-1, max(0, (int)(pt.x*(1.f/16.f))));
        int yi = min(CELLS-1, max(0, (int)(pt.y*(1.f/16.f))));
        atomicAdd(&cnt[yi*CELLS+xi], 1);
    }
    __syncthreads();
    if (tid == 0) {
        int run = 0;
        for (int i = 0; i < CELLS*CELLS; i++) { start[i] = run; run += cnt[i]; }
        start[CELLS*CELLS] = run;
    }
    __syncthreads();
    for (int i = tid; i < CELLS*CELLS; i += 512) cur[i] = start[i];
    for (int i = tid; i <= CELLS*CELLS; i += 512) d_cellstart[b][i] = start[i];
    __syncthreads();
    for (int m = tid; m < NN; m += 512) {
        float4 pt = d_pt[b*NN+m];
        int xi = min(CELLS-1, max(0, (int)(pt.x*(1.f/16.f))));
        int yi = min(CELLS-1, max(0, (int)(pt.y*(1.f/16.f))));
        int pos = atomicAdd(&cur[yi*CELLS+xi], 1);
        d_cellidx[b][pos] = m;
    }
}

// ---------------- pairwise projection via precomposed transforms ----------------
__global__ void k_projpts(const float* __restrict__ points, const float* __restrict__ depths) {
    int t = blockIdx.x*blockDim.x + threadIdx.x;
    unsigned contrib = 0;
    if (t < BB*BB*NN) {
        int i = t / (BB*NN);
        int r = t % (BB*NN);
        int j = r / NN, n = r % NN;
        float pnx = points[(j*NN+n)*2], pny = points[(j*NN+n)*2+1];
        float pxx = (pnx + 1.0f)*(float)(WW-1)*0.5f;
        float pxy = (pny + 1.0f)*(float)(HH-1)*0.5f;
        int xi = (int)fminf(fmaxf(rintf(pxx), 0.f), (float)(WW-1));
        int yi = (int)fminf(fmaxf(rintf(pxy), 0.f), (float)(HH-1));
        float dep = depths[(j*HH + yi)*WW + xi];
        const float* M = d_M[i*BB + j];
        const float* V = d_V[i*BB + j];
        float q0 = M[0]*pxx + M[1]*pxy + M[2];
        float q1 = M[3]*pxx + M[4]*pxy + M[5];
        float q2 = M[6]*pxx + M[7]*pxy + M[8];
        float uu = fmaf(q0, dep, V[0]);
        float vv = fmaf(q1, dep, V[1]);
        float ww = fmaf(q2, dep, V[2]);
        float z = ww;
        float zs = (fabsf(ww) > 1e-6f) ? ww : 1e-6f;
        float u = uu/zs, v = vv/zs;
        bool vis = (z > 0.1f) && (u >= 0.f) && (u <= (float)(WW-1)) && (v >= 0.f) && (v <= (float)(HH-1));
        float un = u*2.0f/(float)(WW-1) - 1.0f;
        float vn = v*2.0f/(float)(HH-1) - 1.0f;
        float dxp = (un + 1.0f)*(float)(WW-1)*0.5f;
        float dyp = (vn + 1.0f)*(float)(HH-1)*0.5f;
        d_nd[t] = make_float4(dxp, dyp, 0.5f - 0.5f*(dxp*dxp + dyp*dyp), 0.f);
        d_vis[t] = vis ? 1 : 0;
        if (vis) contrib = (unsigned)(NN - 1 - n);
    }
    #pragma unroll
    for (int o = 16; o > 0; o >>= 1) contrib += __shfl_xor_sync(~0u, contrib, o);
    if ((threadIdx.x & 31) == 0 && contrib)
        atomicAdd(&d_cnt[1], (unsigned long long)contrib);
}

// ---------------- merged vsum (separable) + psum (spatial grid) ----------------
__global__ __launch_bounds__(256) void k_vp() {   // grid (BB*BB, 4)
    __shared__ float ws[8];
    int ab = blockIdx.x; int a = ab/BB, b = ab%BB;
    int idx = blockIdx.y*256 + threadIdx.x;   // serves as m for vsum and n for psum

    // ---- vsum part (m = idx) ----
    float vloc = 0.f;
    if (d_vis[ab*NN + idx]) {
        const float4* da = (const float4*)(d_descn + ((size_t)a*NN+idx)*DD);
        const float4* ss = (const float4*)(d_S + ((size_t)b*NN+idx)*DD);
        float dot = 0.f;
        #pragma unroll 8
        for (int c = 0; c < 32; c++) {
            float4 x = da[c], y = ss[c];
            dot += x.x*y.x + x.y*y.y + x.z*y.z + x.w*y.w;
        }
        vloc = dot;
    }

    // ---- psum part (n = idx) ----
    float psum = 0.f; unsigned pcnt = 0;
    {
        float4 nd = d_nd[ab*NN + idx];
        if (nd.x >= 13.f && nd.x <= 306.f && nd.y >= 13.f && nd.y <= 306.f) {
            int cx0 = max(0, (int)floorf((nd.x - 1.01f)*(1.f/16.f)));
            int cx1 = min(CELLS-1, (int)floorf((nd.x + 1.01f)*(1.f/16.f)));
            int cy0 = max(0, (int)floorf((nd.y - 1.01f)*(1.f/16.f)));
            int cy1 = min(CELLS-1, (int)floorf((nd.y + 1.01f)*(1.f/16.f)));
            for (int cy = cy0; cy <= cy1; cy++)
            for (int cx = cx0; cx <= cx1; cx++) {
                int c = cy*CELLS + cx;
                int s0 = d_cellstart[b][c], s1 = d_cellstart[b][c+1];
                for (int k = s0; k < s1; k++) {
                    int m = d_cellidx[b][k];
                    if (m >= idx || !d_vis[ab*NN + m]) continue;
                    float4 pt = d_pt[b*NN + m];
                    float tt = fmaf(pt.y, nd.y, nd.z - pt.z);
                    tt = fmaf(pt.x, nd.x, tt);
                    if (tt >= 0.f) {
                        const float4* dm  = (const float4*)(d_descn + ((size_t)a*NN+m)*DD);
                        const float4* dnn = (const float4*)(d_descn + ((size_t)b*NN+idx)*DD);
                        float dot = 0.f;
                        #pragma unroll 8
                        for (int c4 = 0; c4 < 32; c4++) {
                            float4 x = dm[c4], y = dnn[c4];
                            dot += x.x*y.x + x.y*y.y + x.z*y.z + x.w*y.w;
                        }
                        psum += dot; pcnt++;
                    }
                }
            }
        }
    }

    // reductions
    #pragma unroll
    for (int o = 16; o > 0; o >>= 1) {
        vloc += __shfl_xor_sync(~0u, vloc, o);
        psum += __shfl_xor_sync(~0u, psum, o);
        pcnt += __shfl_xor_sync(~0u, pcnt, o);
    }
    int lane = threadIdx.x & 31, w = threadIdx.x >> 5;
    if (lane == 0) {
        ws[w] = vloc;
        if (pcnt) {
            atomicAdd(&d_acc[1], (double)psum);
            atomicAdd(&d_cnt[0], (unsigned long long)pcnt);
        }
    }
    __syncthreads();
    if (w == 0) {
        float v = (lane < 8) ? ws[lane] : 0.f;
        #pragma unroll
        for (int o = 4; o > 0; o >>= 1) v += __shfl_xor_sync(~0u, v, o);
        if (lane == 0) atomicAdd(&d_acc[3], (double)v);
    }
}

// ---------------- diagonal-only FP8 GEMM for distinction (relu-sum) ----------------
__device__ __forceinline__ void ldsm4(unsigned &r0, unsigned &r1, unsigned &r2, unsigned &r3, unsigned addr) {
    asm volatile("ldmatrix.sync.aligned.m8n8.x4.shared.b16 {%0,%1,%2,%3}, [%4];"
                 : "=r"(r0), "=r"(r1), "=r"(r2), "=r"(r3) : "r"(addr));
}
__device__ __forceinline__ void mma8(float* c, const unsigned* a, const unsigned* b) {
    asm volatile("mma.sync.aligned.m16n8k32.row.col.f32.e4m3.e4m3.f32 "
                 "{%0,%1,%2,%3}, {%4,%5,%6,%7}, {%8,%9}, {%0,%1,%2,%3};"
                 : "+f"(c[0]), "+f"(c[1]), "+f"(c[2]), "+f"(c[3])
                 : "r"(a[0]), "r"(a[1]), "r"(a[2]), "r"(a[3]), "r"(b[0]), "r"(b[1]));
}
__device__ __forceinline__ unsigned sw8(int row, int chunk) {
    return (unsigned)(((row << 3) + (chunk ^ (row & 7))) << 4);
}

__global__ __launch_bounds__(256, 3) void k_mdiag(void) {
    int bx = blockIdx.x, by = blockIdx.y;
    if (bx < 2*by) return;
    int a = blockIdx.z;
    bool straddle = ((bx >> 1) == by);
    float dw = straddle ? 1.0f : 2.0f;

    extern __shared__ __align__(16) char dynsmem[];
    char* Asm = dynsmem;
    char* Bsm = dynsmem + 16384;
    __shared__ float wsum[8];

    int m0 = by * 128, n0 = bx * 64;
    int tid = threadIdx.x;
    int lane = tid & 31, warp = tid >> 5;
    int wm = warp >> 1, wn = warp & 1;

    const uint4* Ag = (const uint4*)(d_desc8 + (size_t)(a*NN + m0)*DD);
    const uint4* Bg = (const uint4*)(d_desc8 + (size_t)(a*NN + n0)*DD);
    #pragma unroll
    for (int it = 0; it < 4; it++) {
        int e = tid + it*256;
        int row = e >> 3, ch = e & 7;
        *(uint4*)(Asm + sw8(row, ch)) = Ag[row*8 + ch];
    }
    #pragma unroll
    for (int it = 0; it < 2; it++) {
        int e = tid + it*256;
        int row = e >> 3, ch = e & 7;
        *(uint4*)(Bsm + sw8(row, ch)) = Bg[row*8 + ch];
    }
    __syncthreads();

    unsigned Abase = (unsigned)__cvta_generic_to_shared(Asm);
    unsigned Bbase = (unsigned)__cvta_generic_to_shared(Bsm);

    float acc[2][4][4];
    #pragma unroll
    for (int mi = 0; mi < 2; mi++)
        #pragma unroll
        for (int ni = 0; ni < 4; ni++)
            #pragma unroll
            for (int c = 0; c < 4; c++) acc[mi][ni][c] = 0.f;

    #pragma unroll
    for (int ks = 0; ks < 4; ks++) {
        unsigned af[2][4];
        #pragma unroll
        for (int mi = 0; mi < 2; mi++) {
            int row = wm*32 + mi*16 + (lane & 15);
            int ch  = ks*2 + (lane >> 4);
            ldsm4(af[mi][0], af[mi][1], af[mi][2], af[mi][3], Abase + sw8(row, ch));
        }
        unsigned bf[4][2];
        #pragma unroll
        for (int g = 0; g < 2; g++) {
            int ni0 = g*2;
            int row = wn*32 + (ni0 + (lane >> 4))*8 + (lane & 7);
            int ch  = ks*2 + ((lane >> 3) & 1);
            ldsm4(bf[ni0][0], bf[ni0][1], bf[ni0+1][0], bf[ni0+1][1], Bbase + sw8(row, ch));
        }
        #pragma unroll
        for (int mi = 0; mi < 2; mi++)
            #pragma unroll
            for (int ni = 0; ni < 4; ni++)
                mma8(acc[mi][ni], af[mi], bf[ni]);
    }

    float dsum = 0.f;
    if (straddle) {
        #pragma unroll
        for (int ni = 0; ni < 4; ni++) {
            int nb = n0 + wn*32 + ni*8 + (lane & 3)*2;
            #pragma unroll
            for (int mi = 0; mi < 2; mi++) {
                #pragma unroll
                for (int c = 0; c < 4; c++) {
                    int m = m0 + wm*32 + mi*16 + (c >> 1)*8 + (lane >> 2);
                    int n = nb + (c & 1);
                    float rl = fmaxf(acc[mi][ni][c], 0.f);
                    float wgt = (m < n) ? 2.f : ((m == n) ? 1.f : 0.f);
                    dsum = fmaf(wgt, rl, dsum);
                }
            }
        }
    } else {
        #pragma unroll
        for (int ni = 0; ni < 4; ni++)
            #pragma unroll
            for (int mi = 0; mi < 2; mi++)
                #pragma unroll
                for (int c = 0; c < 4; c++)
                    dsum += fmaxf(acc[mi][ni][c], 0.f);
        dsum *= dw;
    }

    #pragma unroll
    for (int o = 16; o > 0; o >>= 1) dsum += __shfl_xor_sync(~0u, dsum, o);
    if (lane == 0) wsum[warp] = dsum;
    __syncthreads();
    if (warp == 0) {
        float v = (lane < 8) ? wsum[lane] : 0.f;
        #pragma unroll
        for (int o = 4; o > 0; o >>= 1) v += __shfl_xor_sync(~0u, v, o);
        if (lane == 0) atomicAdd(&d_acc[0], (double)v);
    }
}

// ---------------- finalize ----------------
__global__ void k_fin(float* out) {
    double distinction = d_acc[0] / ((double)BB*(double)NN*(double)NN);
    unsigned long long pc = d_cnt[0], tot = d_cnt[1];
    unsigned long long nc = (tot > pc) ? (tot - pc) : 0ULL;
    double pos_mean = d_acc[1] / (double)(pc ? pc : 1ULL);
    double neg_mean = (d_acc[3] - d_acc[1]) / (double)(nc ? nc : 1ULL);
    double match = 1.0 - pos_mean + neg_mean;
    double bce = d_acc[5] / (double)BNP;
    double reg = d_acc[6] / (double)BNP * 10.0;
    out[0] = (float)(distinction + 0.5*(bce + reg) + match);
}

// ---------------- launch ----------------
extern "C" void kernel_launch(void* const* d_in, const int* in_sizes, int n_in,
                              void* d_out, int out_size) {
    const float* desc   = (const float*)d_in[0];
    const float* points = (const float*)d_in[1];
    const float* scores = (const float*)d_in[2];
    const float* depths = (const float*)d_in[3];
    const float* poses  = (const float*)d_in[4];
    const float* Km     = (const float*)d_in[5];
    const float* imgs   = (const float*)d_in[6];
    float* out = (float*)d_out;

    static cudaStream_t s2 = nullptr, s3 = nullptr;
    static cudaEvent_t evFork = nullptr, evPrep = nullptr, evCells = nullptr, evJoin = nullptr, evJoin3 = nullptr;
    static void* tgt_addr = nullptr;
    if (!s2) {
        cudaStreamCreateWithFlags(&s2, cudaStreamNonBlocking);
        cudaStreamCreateWithFlags(&s3, cudaStreamNonBlocking);
        cudaEventCreateWithFlags(&evFork, cudaEventDisableTiming);
        cudaEventCreateWithFlags(&evPrep, cudaEventDisableTiming);
        cudaEventCreateWithFlags(&evCells, cudaEventDisableTiming);
        cudaEventCreateWithFlags(&evJoin, cudaEventDisableTiming);
        cudaEventCreateWithFlags(&evJoin3, cudaEventDisableTiming);
        cudaFuncSetAttribute(k_mdiag, cudaFuncAttributeMaxDynamicSharedMemorySize, 24576);
        cudaFuncSetAttribute(k_front, cudaFuncAttributeMaxDynamicSharedMemorySize, 47104);
        cudaGetSymbolAddress(&tgt_addr, d_target);
    }

    k_init0<<<1, 32>>>();
    cudaMemsetAsync(tgt_addr, 0, BNP*sizeof(float), 0);

    // fork: descriptor chain on s2
    cudaEventRecord(evFork, 0);
    cudaStreamWaitEvent(s2, evFork, 0);
    k_xform<<<1, 64, 0, s2>>>(poses, Km);
    k_prep<<<(BB*NN + 255)/256, 256, 0, s2>>>(points, desc);
    cudaEventRecord(evPrep, s2);

    // s3: cells (needs only prep) then diagonal GEMM
    cudaStreamWaitEvent(s3, evPrep, 0);
    k_cells<<<BB, 512, 0, s3>>>();
    cudaEventRecord(evCells, s3);
    k_mdiag<<<dim3(16, 8, BB), 256, 24576, s3>>>();
    cudaEventRecord(evJoin3, s3);

    // s2 continues: projections, scan, merged vsum+psum
    k_projpts<<<(BB*BB*NN + 255)/256, 256, 0, s2>>>(points, depths);
    k_scan<<<dim3(BB, 4), 1024, 0, s2>>>();
    cudaStreamWaitEvent(s2, evCells, 0);
    k_vp<<<dim3(BB*BB, 4), 256, 0, s2>>>();
    cudaEventRecord(evJoin, s2);

    // image chain on default stream (scatter needs d_M -> wait on evPrep chain via s2? d_M written by k_xform on s2)
    k_front<<<dim3(10, 10, BB), 512, 47104>>>(imgs);
    k_sort<<<BB, 1024>>>();
    cudaStreamWaitEvent(0, evPrep, 0);   // evPrep is after k_xform on s2 -> d_M ready
    k_scatter<<<(BB*BB*NCR + 255)/256, 256>>>(depths, poses, Km);
    k_score<<<dim3(10, 10, BB), 512>>>(scores);

    // join
    cudaStreamWaitEvent(0, evJoin, 0);
    cudaStreamWaitEvent(0, evJoin3, 0);
    k_fin<<<1, 1>>>(out);
}

// round 16
// speedup vs baseline: 1.1255x; 1.1255x over previous
#include <cuda_runtime.h>
#include <cuda_bf16.h>
#include <cuda_fp8.h>
#include <math.h>

#define BB 6
#define HH 320
#define WW 320
#define NP (HH*WW)
#define BNP (BB*NP)
#define NN 1024
#define DD 128
#define NCR 500
#define CAND_MAX 2048
#define CELLS 20
#define NCH 32
#define CHSZ 32

// ---------------- scratch (no allocation allowed) ----------------
__device__ float d_target[BNP];
__device__ int   d_cand_cnt[BB];
__device__ unsigned long long d_cand[BB*CAND_MAX];
__device__ float d_tkval[BB*NCR];
__device__ int   d_tkidx[BB*NCR];

__device__ float4 d_pt[BB*NN];              // (sx, sy, 0.5*x2, -)
__device__ float4 d_nd[BB*BB*NN];           // (dx, dy, 0.5-0.5*y2, -)
__device__ unsigned char d_vis[BB*BB*NN];
__device__ unsigned char d_desc8[BB*NN*DD]; // pre-normalized e4m3 (distinction GEMM)
__device__ float d_descn[BB*NN*DD];         // pre-normalized fp32
__device__ float d_S[BB*NN*DD];             // suffix sums of d_descn over n>m

__device__ float d_M[BB*BB][9];             // K Ri^T Rj Kinv
__device__ float d_V[BB*BB][3];             // K Ri^T (tj - ti)

__device__ int d_cellstart[BB][CELLS*CELLS+1];
__device__ int d_cellidx[BB][NN];

__device__ double d_acc[8];                 // 0 dsum,1 psum,3 vsum,5 bce,6 reg
__device__ unsigned long long d_cnt[2];     // 0 pos count, 1 total vis&triu count
__device__ float d_gw[7];

__device__ __forceinline__ int reflecti(int i, int n){ if (i < 0) i = -i; if (i >= n) i = 2*n-2-i; return i; }
__device__ __forceinline__ int clampi(int i, int n){ return min(max(i,0), n-1); }

// ---------------- tiny init ----------------
__global__ void k_init0() {
    int t = threadIdx.x;
    if (t < 8) d_acc[t] = 0.0;
    if (t < 2) d_cnt[t] = 0ULL;
    if (t < BB) d_cand_cnt[t] = 0;
    if (t == 0) {
        float g[7]; float s = 0.f;
        for (int i = 0; i < 7; i++) { float ax = (float)i - 3.0f; g[i] = expf(-0.5f*ax*ax); s += g[i]; }
        for (int i = 0; i < 7; i++) d_gw[i] = g[i] / s;
    }
}

// ---------------- precompute composed projection transforms (36 pairs) ----------------
__global__ void k_xform(const float* __restrict__ poses, const float* __restrict__ Km) {
    int t = threadIdx.x;
    if (t >= BB*BB) return;
    int i = t / BB, j = t % BB;
    float a00=Km[0],a01=Km[1],a02=Km[2],a10=Km[3],a11=Km[4],a12=Km[5],a20=Km[6],a21=Km[7],a22=Km[8];
    float c00 = a11*a22-a12*a21, c01 = a02*a21-a01*a22, c02 = a01*a12-a02*a11;
    float c10 = a12*a20-a10*a22, c11 = a00*a22-a02*a20, c12 = a02*a10-a00*a12;
    float c20 = a10*a21-a11*a20, c21 = a01*a20-a00*a21, c22 = a00*a11-a01*a10;
    float det = a00*c00 + a01*c10 + a02*c20;
    float id = 1.0f/det;
    float KI[9] = { c00*id, c01*id, c02*id, c10*id, c11*id, c12*id, c20*id, c21*id, c22*id };
    float K[9]  = { a00,a01,a02, a10,a11,a12, a20,a21,a22 };
    const float* Pi = poses + i*16;
    const float* Pj = poses + j*16;
    float A[9], Bm[9];
    for (int r = 0; r < 3; r++)
        for (int c = 0; c < 3; c++) {
            A[r*3+c]  = Pi[c*4+r];
            Bm[r*3+c] = Pj[r*4+c];
        }
    float T1[9], T2[9], M[9];
    for (int r = 0; r < 3; r++)
        for (int c = 0; c < 3; c++)
            T1[r*3+c] = K[r*3+0]*A[c] + K[r*3+1]*A[3+c] + K[r*3+2]*A[6+c];
    for (int r = 0; r < 3; r++)
        for (int c = 0; c < 3; c++)
            T2[r*3+c] = T1[r*3+0]*Bm[c] + T1[r*3+1]*Bm[3+c] + T1[r*3+2]*Bm[6+c];
    for (int r = 0; r < 3; r++)
        for (int c = 0; c < 3; c++)
            M[r*3+c] = T2[r*3+0]*KI[c] + T2[r*3+1]*KI[3+c] + T2[r*3+2]*KI[6+c];
    float dt[3] = { Pj[3]-Pi[3], Pj[7]-Pi[7], Pj[11]-Pi[11] };
    for (int r = 0; r < 9; r++) d_M[t][r] = M[r];
    for (int r = 0; r < 3; r++)
        d_V[t][r] = T1[r*3+0]*dt[0] + T1[r*3+1]*dt[1] + T1[r*3+2]*dt[2];
}

// ---------------- fully-fused gray+sobel+gaussian+GFTT+NMS+blockmax+emit ----------------
__global__ __launch_bounds__(512) void k_front(const float* __restrict__ imgs) {
    extern __shared__ float buf[];
    float* gr = buf;               // 44x44
    float* p0 = buf + 1936;        // 42x42
    float* p1 = p0 + 1764;
    float* p2 = p1 + 1764;
    float* h0 = buf + 7228;        // 42x36
    float* h1 = h0 + 1512;
    float* h2 = h1 + 1512;
    float* rs = buf;               // 36x36 overlays gr
    float* hm = buf + 1936;        // 36x32 overlays p0

    int b = blockIdx.z; int y0 = blockIdx.y*32, x0 = blockIdx.x*32;
    int tid = threadIdx.x;
    const float* base = imgs + (size_t)b*3*NP;

    for (int l = tid; l < 44*44; l += 512) {
        int r = l/44, c = l%44;
        int gy = clampi(y0 + r - 6, HH), gx = clampi(x0 + c - 6, WW);
        int p = gy*WW + gx;
        gr[l] = 0.299f*base[p] + 0.587f*base[NP + p] + 0.114f*base[2*NP + p];
    }
    __syncthreads();

    for (int l = tid; l < 42*42; l += 512) {
        int r = l/42, c = l%42;
        int py = y0 + r - 5, px = x0 + c - 5;
        int ry = reflecti(py, HH), rx = reflecti(px, WW);
        #define GS(yy,xx) gr[(clampi((yy),HH) - (y0-6))*44 + (clampi((xx),WW) - (x0-6))]
        float a00=GS(ry-1,rx-1), a01=GS(ry-1,rx), a02=GS(ry-1,rx+1);
        float a10=GS(ry,  rx-1),                  a12=GS(ry,  rx+1);
        float a20=GS(ry+1,rx-1), a21=GS(ry+1,rx), a22=GS(ry+1,rx+1);
        #undef GS
        float gxv = 0.125f*(a02-a00) + 0.25f*(a12-a10) + 0.125f*(a22-a20);
        float gyv = 0.125f*(a20-a00) + 0.25f*(a21-a01) + 0.125f*(a22-a02);
        p0[l] = gxv*gxv; p1[l] = gyv*gyv; p2[l] = gxv*gyv;
    }
    __syncthreads();

    for (int l = tid; l < 42*36; l += 512) {
        int r = l/36, c = l%36;
        float s0=0.f, s1=0.f, s2=0.f;
        #pragma unroll
        for (int d = 0; d < 7; d++) {
            float w = d_gw[d];
            int q = r*42 + c + d;
            s0 += w*p0[q]; s1 += w*p1[q]; s2 += w*p2[q];
        }
        h0[l]=s0; h1[l]=s1; h2[l]=s2;
    }
    __syncthreads();

    for (int l = tid; l < 36*36; l += 512) {
        int rr = l/36, c = l%36;
        float s0=0.f, s1=0.f, s2=0.f;
        #pragma unroll
        for (int d = 0; d < 7; d++) {
            float w = d_gw[d];
            int q = (rr + d)*36 + c;
            s0 += w*h0[q]; s1 += w*h1[q]; s2 += w*h2[q];
        }
        float tr = s0 + s1, df = s0 - s1;
        float disc = sqrtf(fmaxf(df*df + 4.0f*s2*s2, 0.f));
        float v = 0.5f*(tr - disc);
        int gy = y0 + rr - 2, gx = x0 + c - 2;
        rs[l] = (gy>=0 && gy<HH && gx>=0 && gx<WW) ? v : -INFINITY;
    }
    __syncthreads();

    for (int l = tid; l < 36*32; l += 512) {
        int r = l >> 5, c = l & 31;
        float m = -INFINITY;
        #pragma unroll
        for (int dx = 0; dx < 5; dx++) m = fmaxf(m, rs[r*36 + c + dx]);
        hm[l] = m;
    }
    __syncthreads();

    int lane = tid & 31, w = tid >> 5;
    int br = w >> 2, bc = w & 3;
    float nv[2];
    #pragma unroll
    for (int s = 0; s < 2; s++) {
        int p = lane + s*32;
        int yy = br*8 + (p >> 3), xx = bc*8 + (p & 7);
        float v = rs[(yy+2)*36 + xx + 2];
        float m = -INFINITY;
        #pragma unroll
        for (int dy = 0; dy < 5; dy++) m = fmaxf(m, hm[(yy+dy)*32 + xx]);
        nv[s] = (v == m) ? v : 0.f;
    }
    float bm = fmaxf(nv[0], nv[1]);
    #pragma unroll
    for (int o = 16; o > 0; o >>= 1) bm = fmaxf(bm, __shfl_xor_sync(~0u, bm, o));
    if (bm > 0.f) {
        #pragma unroll
        for (int s = 0; s < 2; s++) {
            if (nv[s] == bm) {
                int p = lane + s*32;
                int gy = y0 + br*8 + (p >> 3), gx = x0 + bc*8 + (p & 7);
                unsigned p_idx = (unsigned)(gy*WW + gx);
                int pos = atomicAdd(&d_cand_cnt[b], 1);
                if (pos < CAND_MAX)
                    d_cand[b*CAND_MAX + pos] =
                        ((unsigned long long)__float_as_uint(bm) << 32) | (unsigned)(~p_idx);
            }
        }
    }
}

// ---------------- per-image bitonic sort + top-500 ----------------
__global__ void k_sort(void) {
    __shared__ unsigned long long s[CAND_MAX];
    int b = blockIdx.x;
    int cnt = min(d_cand_cnt[b], CAND_MAX);
    for (int p = threadIdx.x; p < CAND_MAX; p += blockDim.x)
        s[p] = (p < cnt) ? d_cand[b*CAND_MAX + p] : 0ULL;
    __syncthreads();
    for (int k = 2; k <= CAND_MAX; k <<= 1) {
        for (int j = k >> 1; j > 0; j >>= 1) {
            for (int p = threadIdx.x; p < CAND_MAX; p += blockDim.x) {
                int q = p ^ j;
                if (q > p) {
                    unsigned long long va = s[p], vb = s[q];
                    bool asc = ((p & k) == 0);
                    if ((va < vb) == asc) { s[p] = vb; s[q] = va; }
                }
            }
            __syncthreads();
        }
    }
    for (int p = threadIdx.x; p < NCR; p += blockDim.x) {
        unsigned long long key = s[p];
        float val; int idx;
        if (key == 0ULL) { val = 0.f; idx = 0; }
        else { val = __uint_as_float((unsigned)(key >> 32)); idx = (int)(~(unsigned)key); }
        d_tkval[b*NCR + p] = val;
        d_tkidx[b*NCR + p] = idx;
    }
}

// ---------------- self-contained projection (scatter path; no d_M dependency) ----------------
__device__ __forceinline__ void project_full(
    const float* __restrict__ depths, const float* __restrict__ poses, const float* __restrict__ Km,
    int j, int i, float pxx, float pxy, float& u, float& v, float& z)
{
    int xi = (int)fminf(fmaxf(rintf(pxx), 0.f), (float)(WW-1));
    int yi = (int)fminf(fmaxf(rintf(pxy), 0.f), (float)(HH-1));
    float dep = depths[(j*HH + yi)*WW + xi];
    float a00=Km[0],a01=Km[1],a02=Km[2],a10=Km[3],a11=Km[4],a12=Km[5],a20=Km[6],a21=Km[7],a22=Km[8];
    float c00 = a11*a22-a12*a21, c01 = a02*a21-a01*a22, c02 = a01*a12-a02*a11;
    float c10 = a12*a20-a10*a22, c11 = a00*a22-a02*a20, c12 = a02*a10-a00*a12;
    float c20 = a10*a21-a11*a20, c21 = a01*a20-a00*a21, c22 = a00*a11-a01*a10;
    float det = a00*c00 + a01*c10 + a02*c20;
    float id = 1.0f/det;
    float cx = (c00*pxx + c01*pxy + c02)*id*dep;
    float cy = (c10*pxx + c11*pxy + c12)*id*dep;
    float cz = (c20*pxx + c21*pxy + c22)*id*dep;
    const float* Pj = poses + j*16;
    float wx = Pj[0]*cx + Pj[1]*cy + Pj[2]*cz + Pj[3];
    float wy = Pj[4]*cx + Pj[5]*cy + Pj[6]*cz + Pj[7];
    float wz = Pj[8]*cx + Pj[9]*cy + Pj[10]*cz + Pj[11];
    const float* Pi = poses + i*16;
    float dx = wx - Pi[3], dy = wy - Pi[7], dz = wz - Pi[11];
    float ex = Pi[0]*dx + Pi[4]*dy + Pi[8]*dz;
    float ey = Pi[1]*dx + Pi[5]*dy + Pi[9]*dz;
    float ez = Pi[2]*dx + Pi[6]*dy + Pi[10]*dz;
    float uu = Km[0]*ex + Km[1]*ey + Km[2]*ez;
    float vv = Km[3]*ex + Km[4]*ey + Km[5]*ez;
    float ww = Km[6]*ex + Km[7]*ey + Km[8]*ez;
    z = ww;
    float zs = (fabsf(ww) > 1e-6f) ? ww : 1e-6f;
    u = uu/zs; v = vv/zs;
}

// ---------------- corner project + scatter-max ----------------
__global__ void k_scatter(const float* __restrict__ depths, const float* __restrict__ poses,
                          const float* __restrict__ Km) {
    int t = blockIdx.x*blockDim.x + threadIdx.x;
    if (t >= BB*BB*NCR) return;
    int i = t / (BB*NCR);
    int r = t % (BB*NCR);
    int j = r / NCR, n = r % NCR;
    float val = d_tkval[i*NCR + n];
    if (val <= 0.f) return;
    int idx = d_tkidx[j*NCR + n];
    float cx = (float)(idx % WW), cy = (float)(idx / WW);
    float pnx = cx*2.0f/(float)(WW-1) - 1.0f;
    float pny = cy*2.0f/(float)(HH-1) - 1.0f;
    float pxx = (pnx + 1.0f)*(float)(WW-1)*0.5f;
    float pxy = (pny + 1.0f)*(float)(HH-1)*0.5f;
    float u, v, z;
    project_full(depths, poses, Km, j, i, pxx, pxy, u, v, z);
    bool vis = (z > 0.1f) && (u >= 0.f) && (u <= (float)(WW-1)) && (v >= 0.f) && (v <= (float)(HH-1));
    if (!vis) return;
    float un = u*2.0f/(float)(WW-1) - 1.0f;
    float vn = v*2.0f/(float)(HH-1) - 1.0f;
    float dxp = rintf((un + 1.0f)*(float)(WW-1)*0.5f);
    float dyp = rintf((vn + 1.0f)*(float)(HH-1)*0.5f);
    int ix = (int)dxp, iy = (int)dyp;
    if (dxp >= 0.f && dyp >= 0.f && ix < WW && iy < HH)
        atomicMax((int*)&d_target[j*NP + iy*WW + ix], __float_as_int(val));
}

// ---------------- tiled target NMS + BCE + laplacian reg ----------------
__global__ __launch_bounds__(512) void k_score(const float* __restrict__ scores) {
    __shared__ float tg[36][36], sc[36][36];
    __shared__ float rsum[36][32], rmax[36][32];
    __shared__ float wsum[16][2];
    int b = blockIdx.z; int y0 = blockIdx.y*32, x0 = blockIdx.x*32;
    int tid = threadIdx.x; int lane = tid & 31, w = tid >> 5;
    for (int l = tid; l < 36*36; l += 512) {
        int r = l/36, c = l%36;
        int gy = y0 + r - 2, gx = x0 + c - 2;
        tg[r][c] = (gy>=0 && gy<HH && gx>=0 && gx<WW) ? d_target[b*NP + gy*WW + gx] : -INFINITY;
        int ry = reflecti(gy, HH), rx = reflecti(gx, WW);
        sc[r][c] = scores[b*NP + ry*WW + rx];
    }
    __syncthreads();
    for (int l = tid; l < 36*32; l += 512) {
        int r = l >> 5, c = l & 31;
        float s = 0.f, m = -INFINITY;
        #pragma unroll
        for (int dx = 0; dx < 5; dx++) {
            s += sc[r][c+dx];
            m = fmaxf(m, tg[r][c+dx]);
        }
        rsum[r][c] = s; rmax[r][c] = m;
    }
    __syncthreads();
    int tx = tid & 31, ty0 = tid >> 5;
    float bce = 0.f, reg = 0.f;
    #pragma unroll
    for (int s = 0; s < 2; s++) {
        int r = ty0 + s*16;
        float tv = tg[r+2][tx+2];
        float m = -INFINITY, ssum = 0.f;
        #pragma unroll
        for (int dy = 0; dy < 5; dy++) {
            ssum += rsum[r+dy][tx];
            m = fmaxf(m, rmax[r+dy][tx]);
        }
        bool tb = (tv > 0.f) && (tv == m);
        float sv = sc[r+2][tx+2];
        float pcv = fminf(fmaxf(sv, 1e-12f), 1.0f - 1e-12f);
        bce += -(tb ? logf(pcv) : logf(1.0f - pcv));
        float lap = (ssum - sv)*(1.0f/48.0f) - 0.5f*sv;
        reg += sv*expf(-lap);
    }
    #pragma unroll
    for (int o = 16; o > 0; o >>= 1) {
        bce += __shfl_xor_sync(~0u, bce, o);
        reg += __shfl_xor_sync(~0u, reg, o);
    }
    if (lane == 0) { wsum[w][0] = bce; wsum[w][1] = reg; }
    __syncthreads();
    if (w == 0) {
        float t0 = (lane < 16) ? wsum[lane][0] : 0.f;
        float t1 = (lane < 16) ? wsum[lane][1] : 0.f;
        #pragma unroll
        for (int o = 8; o > 0; o >>= 1) {
            t0 += __shfl_xor_sync(~0u, t0, o);
            t1 += __shfl_xor_sync(~0u, t1, o);
        }
        if (lane == 0) { atomicAdd(&d_acc[5], (double)t0); atomicAdd(&d_acc[6], (double)t1); }
    }
}

// ---------------- per-point prep ----------------
__global__ void k_prep(const float* __restrict__ points, const float* __restrict__ desc) {
    int idx = blockIdx.x*blockDim.x + threadIdx.x;
    if (idx >= BB*NN) return;
    float pnx = points[idx*2], pny = points[idx*2+1];
    float sx = (pnx + 1.0f)*(float)(WW-1)*0.5f;
    float sy = (pny + 1.0f)*(float)(HH-1)*0.5f;
    d_pt[idx] = make_float4(sx, sy, 0.5f*(sx*sx + sy*sy), 0.f);
    const float4* dv = (const float4*)(desc + (size_t)idx*DD);
    float xx = 0.f;
    #pragma unroll
    for (int c = 0; c < 32; c++) {
        float4 v = dv[c];
        xx += v.x*v.x + v.y*v.y + v.z*v.z + v.w*v.w;
    }
    float inv = rsqrtf(fmaxf(xx, 1e-30f));
    float4* on = (float4*)(d_descn + (size_t)idx*DD);
    uint4* ob = (uint4*)(d_desc8 + (size_t)idx*DD);
    #pragma unroll
    for (int c = 0; c < 8; c++) {
        union { unsigned char b[16]; uint4 u; } pk;
        #pragma unroll
        for (int g = 0; g < 4; g++) {
            float4 v = dv[c*4 + g];
            float4 nvv = make_float4(v.x*inv, v.y*inv, v.z*inv, v.w*inv);
            on[c*4 + g] = nvv;
            pk.b[g*4+0] = __nv_fp8_e4m3(nvv.x).__x;
            pk.b[g*4+1] = __nv_fp8_e4m3(nvv.y).__x;
            pk.b[g*4+2] = __nv_fp8_e4m3(nvv.z).__x;
            pk.b[g*4+3] = __nv_fp8_e4m3(nvv.w).__x;
        }
        ob[c] = pk.u;
    }
}

// ---------------- fused parallel suffix scan ----------------
__global__ __launch_bounds__(1024) void k_scan() {
    __shared__ float cs[NCH][33];
    int b = blockIdx.x, dg = blockIdx.y;
    int tid = threadIdx.x;
    int c = tid >> 5, dl = tid & 31;
    int d = dg*32 + dl;
    const float* dn = d_descn + (size_t)b*NN*DD;
    float* S = d_S + (size_t)b*NN*DD;
    float s = 0.f;
    #pragma unroll 8
    for (int n = c*CHSZ; n < c*CHSZ + CHSZ; n++) s += dn[n*DD + d];
    cs[c][dl] = s;
    __syncthreads();
    float run = 0.f;
    for (int cc = c+1; cc < NCH; cc++) run += cs[cc][dl];
    for (int n = c*CHSZ + CHSZ - 1; n >= c*CHSZ; n--) {
        S[n*DD + d] = run;
        run += dn[n*DD + d];
    }
}

// ---------------- spatial grid, parallel prefix (Hillis-Steele over 400 cells) ----------------
__global__ __launch_bounds__(512) void k_cells() {
    __shared__ int cnt[CELLS*CELLS];
    __shared__ int scan[CELLS*CELLS];
    __shared__ int cur[CELLS*CELLS];
    int b = blockIdx.x, tid = threadIdx.x;
    for (int i = tid; i < CELLS*CELLS; i += 512) cnt[i] = 0;
    __syncthreads();
    for (int m = tid; m < NN; m += 512) {
        float4 pt = d_pt[b*NN+m];
        int xi = min(CELLS-1, max(0, (int)(pt.x*(1.f/16.f))));
        int yi = min(CELLS-1, max(0, (int)(pt.y*(1.f/16.f))));
        atomicAdd(&cnt[yi*CELLS+xi], 1);
    }
    __syncthreads();
    // inclusive Hillis-Steele scan over 400 elements
    if (tid < CELLS*CELLS) scan[tid] = cnt[tid];
    __syncthreads();
    for (int off = 1; off < CELLS*CELLS; off <<= 1) {
        int v = 0;
        if (tid < CELLS*CELLS && tid >= off) v = scan[tid - off];
        __syncthreads();
        if (tid < CELLS*CELLS && tid >= off) scan[tid] += v;
        __syncthreads();
    }
    if (tid < CELLS*CELLS) {
        int ex = scan[tid] - cnt[tid];     // exclusive
        d_cellstart[b][tid] = ex;
        cur[tid] = ex;
    }
    if (tid == 0) d_cellstart[b][CELLS*CELLS] = NN;
    __syncthreads();
    for (int m = tid; m < NN; m += 512) {
        float4 pt = d_pt[b*NN+m];
        int xi = min(CELLS-1, max(0, (int)(pt.x*(1.f/16.f))));
        int yi = min(CELLS-1, max(0, (int)(pt.y*(1.f/16.f))));
        int pos = atomicAdd(&cur[yi*CELLS+xi], 1);
        d_cellidx[b][pos] = m;
    }
}

// ---------------- pairwise projection via precomposed transforms ----------------
__global__ void k_projpts(const float* __restrict__ points, const float* __restrict__ depths) {
    int t = blockIdx.x*blockDim.x + threadIdx.x;
    unsigned contrib = 0;
    if (t < BB*BB*NN) {
        int i = t / (BB*NN);
        int r = t % (BB*NN);
        int j = r / NN, n = r % NN;
        float pnx = points[(j*NN+n)*2], pny = points[(j*NN+n)*2+1];
        float pxx = (pnx + 1.0f)*(float)(WW-1)*0.5f;
        float pxy = (pny + 1.0f)*(float)(HH-1)*0.5f;
        int xi = (int)fminf(fmaxf(rintf(pxx), 0.f), (float)(WW-1));
        int yi = (int)fminf(fmaxf(rintf(pxy), 0.f), (float)(HH-1));
        float dep = depths[(j*HH + yi)*WW + xi];
        const float* M = d_M[i*BB + j];
        const float* V = d_V[i*BB + j];
        float q0 = M[0]*pxx + M[1]*pxy + M[2];
        float q1 = M[3]*pxx + M[4]*pxy + M[5];
        float q2 = M[6]*pxx + M[7]*pxy + M[8];
        float uu = fmaf(q0, dep, V[0]);
        float vv = fmaf(q1, dep, V[1]);
        float ww = fmaf(q2, dep, V[2]);
        float z = ww;
        float zs = (fabsf(ww) > 1e-6f) ? ww : 1e-6f;
        float u = uu/zs, v = vv/zs;
        bool vis = (z > 0.1f) && (u >= 0.f) && (u <= (float)(WW-1)) && (v >= 0.f) && (v <= (float)(HH-1));
        float un = u*2.0f/(float)(WW-1) - 1.0f;
        float vn = v*2.0f/(float)(HH-1) - 1.0f;
        float dxp = (un + 1.0f)*(float)(WW-1)*0.5f;
        float dyp = (vn + 1.0f)*(float)(HH-1)*0.5f;
        d_nd[t] = make_float4(dxp, dyp, 0.5f - 0.5f*(dxp*dxp + dyp*dyp), 0.f);
        d_vis[t] = vis ? 1 : 0;
        if (vis) contrib = (unsigned)(NN - 1 - n);
    }
    #pragma unroll
    for (int o = 16; o > 0; o >>= 1) contrib += __shfl_xor_sync(~0u, contrib, o);
    if ((threadIdx.x & 31) == 0 && contrib)
        atomicAdd(&d_cnt[1], (unsigned long long)contrib);
}

// ---------------- merged vsum (separable) + psum (spatial grid) ----------------
__global__ __launch_bounds__(256) void k_vp() {   // grid (BB*BB, 4)
    __shared__ float ws[8];
    int ab = blockIdx.x; int a = ab/BB, b = ab%BB;
    int idx = blockIdx.y*256 + threadIdx.x;

    float vloc = 0.f;
    if (d_vis[ab*NN + idx]) {
        const float4* da = (const float4*)(d_descn + ((size_t)a*NN+idx)*DD);
        const float4* ss = (const float4*)(d_S + ((size_t)b*NN+idx)*DD);
        float dot = 0.f;
        #pragma unroll 8
        for (int c = 0; c < 32; c++) {
            float4 x = da[c], y = ss[c];
            dot += x.x*y.x + x.y*y.y + x.z*y.z + x.w*y.w;
        }
        vloc = dot;
    }

    float psum = 0.f; unsigned pcnt = 0;
    {
        float4 nd = d_nd[ab*NN + idx];
        if (nd.x >= 13.f && nd.x <= 306.f && nd.y >= 13.f && nd.y <= 306.f) {
            int cx0 = max(0, (int)floorf((nd.x - 1.01f)*(1.f/16.f)));
            int cx1 = min(CELLS-1, (int)floorf((nd.x + 1.01f)*(1.f/16.f)));
            int cy0 = max(0, (int)floorf((nd.y - 1.01f)*(1.f/16.f)));
            int cy1 = min(CELLS-1, (int)floorf((nd.y + 1.01f)*(1.f/16.f)));
            for (int cy = cy0; cy <= cy1; cy++)
            for (int cx = cx0; cx <= cx1; cx++) {
                int c = cy*CELLS + cx;
                int s0 = d_cellstart[b][c], s1 = d_cellstart[b][c+1];
                for (int k = s0; k < s1; k++) {
                    int m = d_cellidx[b][k];
                    if (m >= idx || !d_vis[ab*NN + m]) continue;
                    float4 pt = d_pt[b*NN + m];
                    float tt = fmaf(pt.y, nd.y, nd.z - pt.z);
                    tt = fmaf(pt.x, nd.x, tt);
                    if (tt >= 0.f) {
                        const float4* dm  = (const float4*)(d_descn + ((size_t)a*NN+m)*DD);
                        const float4* dnn = (const float4*)(d_descn + ((size_t)b*NN+idx)*DD);
                        float dot = 0.f;
                        #pragma unroll 8
                        for (int c4 = 0; c4 < 32; c4++) {
                            float4 x = dm[c4], y = dnn[c4];
                            dot += x.x*y.x + x.y*y.y + x.z*y.z + x.w*y.w;
                        }
                        psum += dot; pcnt++;
                    }
                }
            }
        }
    }

    #pragma unroll
    for (int o = 16; o > 0; o >>= 1) {
        vloc += __shfl_xor_sync(~0u, vloc, o);
        psum += __shfl_xor_sync(~0u, psum, o);
        pcnt += __shfl_xor_sync(~0u, pcnt, o);
    }
    int lane = threadIdx.x & 31, w = threadIdx.x >> 5;
    if (lane == 0) {
        ws[w] = vloc;
        if (pcnt) {
            atomicAdd(&d_acc[1], (double)psum);
            atomicAdd(&d_cnt[0], (unsigned long long)pcnt);
        }
    }
    __syncthreads();
    if (w == 0) {
        float v = (lane < 8) ? ws[lane] : 0.f;
        #pragma unroll
        for (int o = 4; o > 0; o >>= 1) v += __shfl_xor_sync(~0u, v, o);
        if (lane == 0) atomicAdd(&d_acc[3], (double)v);
    }
}

// ---------------- diagonal-only FP8 GEMM for distinction (relu-sum) ----------------
__device__ __forceinline__ void ldsm4(unsigned &r0, unsigned &r1, unsigned &r2, unsigned &r3, unsigned addr) {
    asm volatile("ldmatrix.sync.aligned.m8n8.x4.shared.b16 {%0,%1,%2,%3}, [%4];"
                 : "=r"(r0), "=r"(r1), "=r"(r2), "=r"(r3) : "r"(addr));
}
__device__ __forceinline__ void mma8(float* c, const unsigned* a, const unsigned* b) {
    asm volatile("mma.sync.aligned.m16n8k32.row.col.f32.e4m3.e4m3.f32 "
                 "{%0,%1,%2,%3}, {%4,%5,%6,%7}, {%8,%9}, {%0,%1,%2,%3};"
                 : "+f"(c[0]), "+f"(c[1]), "+f"(c[2]), "+f"(c[3])
                 : "r"(a[0]), "r"(a[1]), "r"(a[2]), "r"(a[3]), "r"(b[0]), "r"(b[1]));
}
__device__ __forceinline__ unsigned sw8(int row, int chunk) {
    return (unsigned)(((row << 3) + (chunk ^ (row & 7))) << 4);
}

__global__ __launch_bounds__(256, 3) void k_mdiag(void) {
    int bx = blockIdx.x, by = blockIdx.y;
    if (bx < 2*by) return;
    int a = blockIdx.z;
    bool straddle = ((bx >> 1) == by);
    float dw = straddle ? 1.0f : 2.0f;

    extern __shared__ __align__(16) char dynsmem[];
    char* Asm = dynsmem;
    char* Bsm = dynsmem + 16384;
    __shared__ float wsum[8];

    int m0 = by * 128, n0 = bx * 64;
    int tid = threadIdx.x;
    int lane = tid & 31, warp = tid >> 5;
    int wm = warp >> 1, wn = warp & 1;

    const uint4* Ag = (const uint4*)(d_desc8 + (size_t)(a*NN + m0)*DD);
    const uint4* Bg = (const uint4*)(d_desc8 + (size_t)(a*NN + n0)*DD);
    #pragma unroll
    for (int it = 0; it < 4; it++) {
        int e = tid + it*256;
        int row = e >> 3, ch = e & 7;
        *(uint4*)(Asm + sw8(row, ch)) = Ag[row*8 + ch];
    }
    #pragma unroll
    for (int it = 0; it < 2; it++) {
        int e = tid + it*256;
        int row = e >> 3, ch = e & 7;
        *(uint4*)(Bsm + sw8(row, ch)) = Bg[row*8 + ch];
    }
    __syncthreads();

    unsigned Abase = (unsigned)__cvta_generic_to_shared(Asm);
    unsigned Bbase = (unsigned)__cvta_generic_to_shared(Bsm);

    float acc[2][4][4];
    #pragma unroll
    for (int mi = 0; mi < 2; mi++)
        #pragma unroll
        for (int ni = 0; ni < 4; ni++)
            #pragma unroll
            for (int c = 0; c < 4; c++) acc[mi][ni][c] = 0.f;

    #pragma unroll
    for (int ks = 0; ks < 4; ks++) {
        unsigned af[2][4];
        #pragma unroll
        for (int mi = 0; mi < 2; mi++) {
            int row = wm*32 + mi*16 + (lane & 15);
            int ch  = ks*2 + (lane >> 4);
            ldsm4(af[mi][0], af[mi][1], af[mi][2], af[mi][3], Abase + sw8(row, ch));
        }
        unsigned bf[4][2];
        #pragma unroll
        for (int g = 0; g < 2; g++) {
            int ni0 = g*2;
            int row = wn*32 + (ni0 + (lane >> 4))*8 + (lane & 7);
            int ch  = ks*2 + ((lane >> 3) & 1);
            ldsm4(bf[ni0][0], bf[ni0][1], bf[ni0+1][0], bf[ni0+1][1], Bbase + sw8(row, ch));
        }
        #pragma unroll
        for (int mi = 0; mi < 2; mi++)
            #pragma unroll
            for (int ni = 0; ni < 4; ni++)
                mma8(acc[mi][ni], af[mi], bf[ni]);
    }

    float dsum = 0.f;
    if (straddle) {
        #pragma unroll
        for (int ni = 0; ni < 4; ni++) {
            int nb = n0 + wn*32 + ni*8 + (lane & 3)*2;
            #pragma unroll
            for (int mi = 0; mi < 2; mi++) {
                #pragma unroll
                for (int c = 0; c < 4; c++) {
                    int m = m0 + wm*32 + mi*16 + (c >> 1)*8 + (lane >> 2);
                    int n = nb + (c & 1);
                    float rl = fmaxf(acc[mi][ni][c], 0.f);
                    float wgt = (m < n) ? 2.f : ((m == n) ? 1.f : 0.f);
                    dsum = fmaf(wgt, rl, dsum);
                }
            }
        }
    } else {
        #pragma unroll
        for (int ni = 0; ni < 4; ni++)
            #pragma unroll
            for (int mi = 0; mi < 2; mi++)
                #pragma unroll
                for (int c = 0; c < 4; c++)
                    dsum += fmaxf(acc[mi][ni][c], 0.f);
        dsum *= dw;
    }

    #pragma unroll
    for (int o = 16; o > 0; o >>= 1) dsum += __shfl_xor_sync(~0u, dsum, o);
    if (lane == 0) wsum[warp] = dsum;
    __syncthreads();
    if (warp == 0) {
        float v = (lane < 8) ? wsum[lane] : 0.f;
        #pragma unroll
        for (int o = 4; o > 0; o >>= 1) v += __shfl_xor_sync(~0u, v, o);
        if (lane == 0) atomicAdd(&d_acc[0], (double)v);
    }
}

// ---------------- finalize ----------------
__global__ void k_fin(float* out) {
    double distinction = d_acc[0] / ((double)BB*(double)NN*(double)NN);
    unsigned long long pc = d_cnt[0], tot = d_cnt[1];
    unsigned long long nc = (tot > pc) ? (tot - pc) : 0ULL;
    double pos_mean = d_acc[1] / (double)(pc ? pc : 1ULL);
    double neg_mean = (d_acc[3] - d_acc[1]) / (double)(nc ? nc : 1ULL);
    double match = 1.0 - pos_mean + neg_mean;
    double bce = d_acc[5] / (double)BNP;
    double reg = d_acc[6] / (double)BNP * 10.0;
    out[0] = (float)(distinction + 0.5*(bce + reg) + match);
}

// ---------------- launch ----------------
extern "C" void kernel_launch(void* const* d_in, const int* in_sizes, int n_in,
                              void* d_out, int out_size) {
    const float* desc   = (const float*)d_in[0];
    const float* points = (const float*)d_in[1];
    const float* scores = (const float*)d_in[2];
    const float* depths = (const float*)d_in[3];
    const float* poses  = (const float*)d_in[4];
    const float* Km     = (const float*)d_in[5];
    const float* imgs   = (const float*)d_in[6];
    float* out = (float*)d_out;

    static cudaStream_t s2 = nullptr, s3 = nullptr;
    static cudaEvent_t evFork = nullptr, evPrep = nullptr, evJoin = nullptr, evJoin3 = nullptr;
    static void* tgt_addr = nullptr;
    if (!s2) {
        cudaStreamCreateWithFlags(&s2, cudaStreamNonBlocking);
        cudaStreamCreateWithFlags(&s3, cudaStreamNonBlocking);
        cudaEventCreateWithFlags(&evFork, cudaEventDisableTiming);
        cudaEventCreateWithFlags(&evPrep, cudaEventDisableTiming);
        cudaEventCreateWithFlags(&evJoin, cudaEventDisableTiming);
        cudaEventCreateWithFlags(&evJoin3, cudaEventDisableTiming);
        cudaFuncSetAttribute(k_mdiag, cudaFuncAttributeMaxDynamicSharedMemorySize, 24576);
        cudaFuncSetAttribute(k_front, cudaFuncAttributeMaxDynamicSharedMemorySize, 47104);
        cudaGetSymbolAddress(&tgt_addr, d_target);
    }

    k_init0<<<1, 32>>>();
    cudaMemsetAsync(tgt_addr, 0, BNP*sizeof(float), 0);

    // fork: descriptor chain on s2
    cudaEventRecord(evFork, 0);
    cudaStreamWaitEvent(s2, evFork, 0);
    k_xform<<<1, 64, 0, s2>>>(poses, Km);
    k_prep<<<(BB*NN + 255)/256, 256, 0, s2>>>(points, desc);
    cudaEventRecord(evPrep, s2);

    // s3: diagonal GEMM (needs only prep)
    cudaStreamWaitEvent(s3, evPrep, 0);
    k_mdiag<<<dim3(16, 8, BB), 256, 24576, s3>>>();
    cudaEventRecord(evJoin3, s3);

    // s2 continues: projections, scan, cells, merged vsum+psum
    k_projpts<<<(BB*BB*NN + 255)/256, 256, 0, s2>>>(points, depths);
    k_scan<<<dim3(BB, 4), 1024, 0, s2>>>();
    k_cells<<<BB, 512, 0, s2>>>();
    k_vp<<<dim3(BB*BB, 4), 256, 0, s2>>>();
    cudaEventRecord(evJoin, s2);

    // image chain on default stream (fully independent)
    k_front<<<dim3(10, 10, BB), 512, 47104>>>(imgs);
    k_sort<<<BB, 1024>>>();
    k_scatter<<<(BB*BB*NCR + 255)/256, 256>>>(depths, poses, Km);
    k_score<<<dim3(10, 10, BB), 512>>>(scores);

    // join
    cudaStreamWaitEvent(0, evJoin, 0);
    cudaStreamWaitEvent(0, evJoin3, 0);
    k_fin<<<1, 1>>>(out);
}

// round 17
// speedup vs baseline: 1.4327x; 1.2730x over previous
#include <cuda_runtime.h>
#include <cuda_bf16.h>
#include <cuda_fp8.h>
#include <math.h>

#define BB 6
#define HH 320
#define WW 320
#define NP (HH*WW)
#define BNP (BB*NP)
#define NN 1024
#define DD 128
#define NCR 500
#define CAND_MAX 2048
#define CELLS 20
#define NCH 32
#define CHSZ 32

// ---------------- scratch (no allocation allowed) ----------------
struct ZeroBlob {
    float target[BNP];
    double acc[8];                  // 0 dsum,1 psum,3 vsum,5 bce,6 reg
    unsigned long long cnt[2];      // 0 pos count, 1 total vis&triu count
    int cand_cnt[BB];
};
__device__ ZeroBlob d_z;

__device__ unsigned long long d_cand[BB*CAND_MAX];
__device__ float d_tkval[BB*NCR];
__device__ int   d_tkidx[BB*NCR];

__device__ float4 d_pt[BB*NN];              // (sx, sy, 0.5*x2, -)
__device__ float4 d_nd[BB*BB*NN];           // (dx, dy, 0.5-0.5*y2, -)
__device__ unsigned char d_vis[BB*BB*NN];
__device__ unsigned char d_desc8[BB*NN*DD]; // pre-normalized e4m3
__device__ float d_descn[BB*NN*DD];         // pre-normalized fp32
__device__ float d_S[BB*NN*DD];             // suffix sums over n>m

__device__ int d_cellstart[BB][CELLS*CELLS+1];
__device__ int d_cellidx[BB][NN];

__device__ __forceinline__ int reflecti(int i, int n){ if (i < 0) i = -i; if (i >= n) i = 2*n-2-i; return i; }
__device__ __forceinline__ int clampi(int i, int n){ return min(max(i,0), n-1); }

// ---------------- fully-fused gray+sobel+gaussian+GFTT+NMS+blockmax+emit ----------------
__global__ __launch_bounds__(512) void k_front(const float* __restrict__ imgs) {
    extern __shared__ float buf[];
    float* gr = buf;               // 44x44
    float* p0 = buf + 1936;        // 42x42
    float* p1 = p0 + 1764;
    float* p2 = p1 + 1764;
    float* h0 = buf + 7228;        // 42x36
    float* h1 = h0 + 1512;
    float* h2 = h1 + 1512;
    float* rs = buf;               // 36x36 overlays gr
    float* hm = buf + 1936;        // 36x32 overlays p0
    __shared__ float gw[7];

    int b = blockIdx.z; int y0 = blockIdx.y*32, x0 = blockIdx.x*32;
    int tid = threadIdx.x;
    const float* base = imgs + (size_t)b*3*NP;

    if (tid == 0) {
        float g[7]; float s = 0.f;
        #pragma unroll
        for (int i = 0; i < 7; i++) { float ax = (float)i - 3.0f; g[i] = expf(-0.5f*ax*ax); s += g[i]; }
        #pragma unroll
        for (int i = 0; i < 7; i++) gw[i] = g[i] / s;
    }

    for (int l = tid; l < 44*44; l += 512) {
        int r = l/44, c = l%44;
        int gy = clampi(y0 + r - 6, HH), gx = clampi(x0 + c - 6, WW);
        int p = gy*WW + gx;
        gr[l] = 0.299f*base[p] + 0.587f*base[NP + p] + 0.114f*base[2*NP + p];
    }
    __syncthreads();

    for (int l = tid; l < 42*42; l += 512) {
        int r = l/42, c = l%42;
        int py = y0 + r - 5, px = x0 + c - 5;
        int ry = reflecti(py, HH), rx = reflecti(px, WW);
        #define GS(yy,xx) gr[(clampi((yy),HH) - (y0-6))*44 + (clampi((xx),WW) - (x0-6))]
        float a00=GS(ry-1,rx-1), a01=GS(ry-1,rx), a02=GS(ry-1,rx+1);
        float a10=GS(ry,  rx-1),                  a12=GS(ry,  rx+1);
        float a20=GS(ry+1,rx-1), a21=GS(ry+1,rx), a22=GS(ry+1,rx+1);
        #undef GS
        float gxv = 0.125f*(a02-a00) + 0.25f*(a12-a10) + 0.125f*(a22-a20);
        float gyv = 0.125f*(a20-a00) + 0.25f*(a21-a01) + 0.125f*(a22-a02);
        p0[l] = gxv*gxv; p1[l] = gyv*gyv; p2[l] = gxv*gyv;
    }
    __syncthreads();

    for (int l = tid; l < 42*36; l += 512) {
        int r = l/36, c = l%36;
        float s0=0.f, s1=0.f, s2=0.f;
        #pragma unroll
        for (int d = 0; d < 7; d++) {
            float w = gw[d];
            int q = r*42 + c + d;
            s0 += w*p0[q]; s1 += w*p1[q]; s2 += w*p2[q];
        }
        h0[l]=s0; h1[l]=s1; h2[l]=s2;
    }
    __syncthreads();

    for (int l = tid; l < 36*36; l += 512) {
        int rr = l/36, c = l%36;
        float s0=0.f, s1=0.f, s2=0.f;
        #pragma unroll
        for (int d = 0; d < 7; d++) {
            float w = gw[d];
            int q = (rr + d)*36 + c;
            s0 += w*h0[q]; s1 += w*h1[q]; s2 += w*h2[q];
        }
        float tr = s0 + s1, df = s0 - s1;
        float disc = sqrtf(fmaxf(df*df + 4.0f*s2*s2, 0.f));
        float v = 0.5f*(tr - disc);
        int gy = y0 + rr - 2, gx = x0 + c - 2;
        rs[l] = (gy>=0 && gy<HH && gx>=0 && gx<WW) ? v : -INFINITY;
    }
    __syncthreads();

    for (int l = tid; l < 36*32; l += 512) {
        int r = l >> 5, c = l & 31;
        float m = -INFINITY;
        #pragma unroll
        for (int dx = 0; dx < 5; dx++) m = fmaxf(m, rs[r*36 + c + dx]);
        hm[l] = m;
    }
    __syncthreads();

    int lane = tid & 31, w = tid >> 5;
    int br = w >> 2, bc = w & 3;
    float nv[2];
    #pragma unroll
    for (int s = 0; s < 2; s++) {
        int p = lane + s*32;
        int yy = br*8 + (p >> 3), xx = bc*8 + (p & 7);
        float v = rs[(yy+2)*36 + xx + 2];
        float m = -INFINITY;
        #pragma unroll
        for (int dy = 0; dy < 5; dy++) m = fmaxf(m, hm[(yy+dy)*32 + xx]);
        nv[s] = (v == m) ? v : 0.f;
    }
    float bm = fmaxf(nv[0], nv[1]);
    #pragma unroll
    for (int o = 16; o > 0; o >>= 1) bm = fmaxf(bm, __shfl_xor_sync(~0u, bm, o));
    if (bm > 0.f) {
        #pragma unroll
        for (int s = 0; s < 2; s++) {
            if (nv[s] == bm) {
                int p = lane + s*32;
                int gy = y0 + br*8 + (p >> 3), gx = x0 + bc*8 + (p & 7);
                unsigned p_idx = (unsigned)(gy*WW + gx);
                int pos = atomicAdd(&d_z.cand_cnt[b], 1);
                if (pos < CAND_MAX)
                    d_cand[b*CAND_MAX + pos] =
                        ((unsigned long long)__float_as_uint(bm) << 32) | (unsigned)(~p_idx);
            }
        }
    }
}

// ---------------- per-image bitonic sort + top-500 ----------------
__global__ void k_sort(void) {
    __shared__ unsigned long long s[CAND_MAX];
    int b = blockIdx.x;
    int cnt = min(d_z.cand_cnt[b], CAND_MAX);
    for (int p = threadIdx.x; p < CAND_MAX; p += blockDim.x)
        s[p] = (p < cnt) ? d_cand[b*CAND_MAX + p] : 0ULL;
    __syncthreads();
    for (int k = 2; k <= CAND_MAX; k <<= 1) {
        for (int j = k >> 1; j > 0; j >>= 1) {
            for (int p = threadIdx.x; p < CAND_MAX; p += blockDim.x) {
                int q = p ^ j;
                if (q > p) {
                    unsigned long long va = s[p], vb = s[q];
                    bool asc = ((p & k) == 0);
                    if ((va < vb) == asc) { s[p] = vb; s[q] = va; }
                }
            }
            __syncthreads();
        }
    }
    for (int p = threadIdx.x; p < NCR; p += blockDim.x) {
        unsigned long long key = s[p];
        float val; int idx;
        if (key == 0ULL) { val = 0.f; idx = 0; }
        else { val = __uint_as_float((unsigned)(key >> 32)); idx = (int)(~(unsigned)key); }
        d_tkval[b*NCR + p] = val;
        d_tkidx[b*NCR + p] = idx;
    }
}

// ---------------- self-contained projection (scatter path) ----------------
__device__ __forceinline__ void project_full(
    const float* __restrict__ depths, const float* __restrict__ poses, const float* __restrict__ Km,
    int j, int i, float pxx, float pxy, float& u, float& v, float& z)
{
    int xi = (int)fminf(fmaxf(rintf(pxx), 0.f), (float)(WW-1));
    int yi = (int)fminf(fmaxf(rintf(pxy), 0.f), (float)(HH-1));
    float dep = depths[(j*HH + yi)*WW + xi];
    float a00=Km[0],a01=Km[1],a02=Km[2],a10=Km[3],a11=Km[4],a12=Km[5],a20=Km[6],a21=Km[7],a22=Km[8];
    float c00 = a11*a22-a12*a21, c01 = a02*a21-a01*a22, c02 = a01*a12-a02*a11;
    float c10 = a12*a20-a10*a22, c11 = a00*a22-a02*a20, c12 = a02*a10-a00*a12;
    float c20 = a10*a21-a11*a20, c21 = a01*a20-a00*a21, c22 = a00*a11-a01*a10;
    float det = a00*c00 + a01*c10 + a02*c20;
    float id = 1.0f/det;
    float cx = (c00*pxx + c01*pxy + c02)*id*dep;
    float cy = (c10*pxx + c11*pxy + c12)*id*dep;
    float cz = (c20*pxx + c21*pxy + c22)*id*dep;
    const float* Pj = poses + j*16;
    float wx = Pj[0]*cx + Pj[1]*cy + Pj[2]*cz + Pj[3];
    float wy = Pj[4]*cx + Pj[5]*cy + Pj[6]*cz + Pj[7];
    float wz = Pj[8]*cx + Pj[9]*cy + Pj[10]*cz + Pj[11];
    const float* Pi = poses + i*16;
    float dx = wx - Pi[3], dy = wy - Pi[7], dz = wz - Pi[11];
    float ex = Pi[0]*dx + Pi[4]*dy + Pi[8]*dz;
    float ey = Pi[1]*dx + Pi[5]*dy + Pi[9]*dz;
    float ez = Pi[2]*dx + Pi[6]*dy + Pi[10]*dz;
    float uu = Km[0]*ex + Km[1]*ey + Km[2]*ez;
    float vv = Km[3]*ex + Km[4]*ey + Km[5]*ez;
    float ww = Km[6]*ex + Km[7]*ey + Km[8]*ez;
    z = ww;
    float zs = (fabsf(ww) > 1e-6f) ? ww : 1e-6f;
    u = uu/zs; v = vv/zs;
}

// ---------------- corner project + scatter-max ----------------
__global__ void k_scatter(const float* __restrict__ depths, const float* __restrict__ poses,
                          const float* __restrict__ Km) {
    int t = blockIdx.x*blockDim.x + threadIdx.x;
    if (t >= BB*BB*NCR) return;
    int i = t / (BB*NCR);
    int r = t % (BB*NCR);
    int j = r / NCR, n = r % NCR;
    float val = d_tkval[i*NCR + n];
    if (val <= 0.f) return;
    int idx = d_tkidx[j*NCR + n];
    float cx = (float)(idx % WW), cy = (float)(idx / WW);
    float pnx = cx*2.0f/(float)(WW-1) - 1.0f;
    float pny = cy*2.0f/(float)(HH-1) - 1.0f;
    float pxx = (pnx + 1.0f)*(float)(WW-1)*0.5f;
    float pxy = (pny + 1.0f)*(float)(HH-1)*0.5f;
    float u, v, z;
    project_full(depths, poses, Km, j, i, pxx, pxy, u, v, z);
    bool vis = (z > 0.1f) && (u >= 0.f) && (u <= (float)(WW-1)) && (v >= 0.f) && (v <= (float)(HH-1));
    if (!vis) return;
    float un = u*2.0f/(float)(WW-1) - 1.0f;
    float vn = v*2.0f/(float)(HH-1) - 1.0f;
    float dxp = rintf((un + 1.0f)*(float)(WW-1)*0.5f);
    float dyp = rintf((vn + 1.0f)*(float)(HH-1)*0.5f);
    int ix = (int)dxp, iy = (int)dyp;
    if (dxp >= 0.f && dyp >= 0.f && ix < WW && iy < HH)
        atomicMax((int*)&d_z.target[j*NP + iy*WW + ix], __float_as_int(val));
}

// ---------------- tiled target NMS + BCE + laplacian reg ----------------
__global__ __launch_bounds__(512) void k_score(const float* __restrict__ scores) {
    __shared__ float tg[36][36], sc[36][36];
    __shared__ float rsum[36][32], rmax[36][32];
    __shared__ float wsum[16][2];
    int b = blockIdx.z; int y0 = blockIdx.y*32, x0 = blockIdx.x*32;
    int tid = threadIdx.x; int lane = tid & 31, w = tid >> 5;
    for (int l = tid; l < 36*36; l += 512) {
        int r = l/36, c = l%36;
        int gy = y0 + r - 2, gx = x0 + c - 2;
        tg[r][c] = (gy>=0 && gy<HH && gx>=0 && gx<WW) ? d_z.target[b*NP + gy*WW + gx] : -INFINITY;
        int ry = reflecti(gy, HH), rx = reflecti(gx, WW);
        sc[r][c] = scores[b*NP + ry*WW + rx];
    }
    __syncthreads();
    for (int l = tid; l < 36*32; l += 512) {
        int r = l >> 5, c = l & 31;
        float s = 0.f, m = -INFINITY;
        #pragma unroll
        for (int dx = 0; dx < 5; dx++) {
            s += sc[r][c+dx];
            m = fmaxf(m, tg[r][c+dx]);
        }
        rsum[r][c] = s; rmax[r][c] = m;
    }
    __syncthreads();
    int tx = tid & 31, ty0 = tid >> 5;
    float bce = 0.f, reg = 0.f;
    #pragma unroll
    for (int s = 0; s < 2; s++) {
        int r = ty0 + s*16;
        float tv = tg[r+2][tx+2];
        float m = -INFINITY, ssum = 0.f;
        #pragma unroll
        for (int dy = 0; dy < 5; dy++) {
            ssum += rsum[r+dy][tx];
            m = fmaxf(m, rmax[r+dy][tx]);
        }
        bool tb = (tv > 0.f) && (tv == m);
        float sv = sc[r+2][tx+2];
        float pcv = fminf(fmaxf(sv, 1e-12f), 1.0f - 1e-12f);
        bce += -(tb ? logf(pcv) : logf(1.0f - pcv));
        float lap = (ssum - sv)*(1.0f/48.0f) - 0.5f*sv;
        reg += sv*expf(-lap);
    }
    #pragma unroll
    for (int o = 16; o > 0; o >>= 1) {
        bce += __shfl_xor_sync(~0u, bce, o);
        reg += __shfl_xor_sync(~0u, reg, o);
    }
    if (lane == 0) { wsum[w][0] = bce; wsum[w][1] = reg; }
    __syncthreads();
    if (w == 0) {
        float t0 = (lane < 16) ? wsum[lane][0] : 0.f;
        float t1 = (lane < 16) ? wsum[lane][1] : 0.f;
        #pragma unroll
        for (int o = 8; o > 0; o >>= 1) {
            t0 += __shfl_xor_sync(~0u, t0, o);
            t1 += __shfl_xor_sync(~0u, t1, o);
        }
        if (lane == 0) { atomicAdd(&d_z.acc[5], (double)t0); atomicAdd(&d_z.acc[6], (double)t1); }
    }
}

// ---------------- per-point prep ----------------
__global__ void k_prep(const float* __restrict__ points, const float* __restrict__ desc) {
    int idx = blockIdx.x*blockDim.x + threadIdx.x;
    if (idx >= BB*NN) return;
    float pnx = points[idx*2], pny = points[idx*2+1];
    float sx = (pnx + 1.0f)*(float)(WW-1)*0.5f;
    float sy = (pny + 1.0f)*(float)(HH-1)*0.5f;
    d_pt[idx] = make_float4(sx, sy, 0.5f*(sx*sx + sy*sy), 0.f);
    const float4* dv = (const float4*)(desc + (size_t)idx*DD);
    float xx = 0.f;
    #pragma unroll
    for (int c = 0; c < 32; c++) {
        float4 v = dv[c];
        xx += v.x*v.x + v.y*v.y + v.z*v.z + v.w*v.w;
    }
    float inv = rsqrtf(fmaxf(xx, 1e-30f));
    float4* on = (float4*)(d_descn + (size_t)idx*DD);
    uint4* ob = (uint4*)(d_desc8 + (size_t)idx*DD);
    #pragma unroll
    for (int c = 0; c < 8; c++) {
        union { unsigned char b[16]; uint4 u; } pk;
        #pragma unroll
        for (int g = 0; g < 4; g++) {
            float4 v = dv[c*4 + g];
            float4 nvv = make_float4(v.x*inv, v.y*inv, v.z*inv, v.w*inv);
            on[c*4 + g] = nvv;
            pk.b[g*4+0] = __nv_fp8_e4m3(nvv.x).__x;
            pk.b[g*4+1] = __nv_fp8_e4m3(nvv.y).__x;
            pk.b[g*4+2] = __nv_fp8_e4m3(nvv.z).__x;
            pk.b[g*4+3] = __nv_fp8_e4m3(nvv.w).__x;
        }
        ob[c] = pk.u;
    }
}

// ---------------- fused parallel suffix scan + (dg==3) spatial-grid build ----------------
__global__ __launch_bounds__(1024) void k_scan() {
    __shared__ float cs[NCH][33];
    __shared__ int cnt[CELLS*CELLS];
    __shared__ int scn[CELLS*CELLS];
    __shared__ int cur[CELLS*CELLS];
    int b = blockIdx.x, dg = blockIdx.y;
    int tid = threadIdx.x;
    int c = tid >> 5, dl = tid & 31;
    int d = dg*32 + dl;
    const float* dn = d_descn + (size_t)b*NN*DD;
    float* S = d_S + (size_t)b*NN*DD;
    float s = 0.f;
    #pragma unroll 8
    for (int n = c*CHSZ; n < c*CHSZ + CHSZ; n++) s += dn[n*DD + d];
    cs[c][dl] = s;
    __syncthreads();
    float run = 0.f;
    for (int cc = c+1; cc < NCH; cc++) run += cs[cc][dl];
    for (int n = c*CHSZ + CHSZ - 1; n >= c*CHSZ; n--) {
        S[n*DD + d] = run;
        run += dn[n*DD + d];
    }
    // cells build (one block per image does it)
    if (dg == 3) {
        if (tid < CELLS*CELLS) cnt[tid] = 0;
        __syncthreads();
        {
            float4 pt = d_pt[b*NN + tid];
            int xi = min(CELLS-1, max(0, (int)(pt.x*(1.f/16.f))));
            int yi = min(CELLS-1, max(0, (int)(pt.y*(1.f/16.f))));
            atomicAdd(&cnt[yi*CELLS+xi], 1);
        }
        __syncthreads();
        if (tid < CELLS*CELLS) scn[tid] = cnt[tid];
        __syncthreads();
        for (int off = 1; off < CELLS*CELLS; off <<= 1) {
            int v = 0;
            if (tid < CELLS*CELLS && tid >= off) v = scn[tid - off];
            __syncthreads();
            if (tid < CELLS*CELLS && tid >= off) scn[tid] += v;
            __syncthreads();
        }
        if (tid < CELLS*CELLS) {
            int ex = scn[tid] - cnt[tid];
            d_cellstart[b][tid] = ex;
            cur[tid] = ex;
        }
        if (tid == 0) d_cellstart[b][CELLS*CELLS] = NN;
        __syncthreads();
        {
            float4 pt = d_pt[b*NN + tid];
            int xi = min(CELLS-1, max(0, (int)(pt.x*(1.f/16.f))));
            int yi = min(CELLS-1, max(0, (int)(pt.y*(1.f/16.f))));
            int pos = atomicAdd(&cur[yi*CELLS+xi], 1);
            d_cellidx[b][pos] = tid;
        }
    }
}

// ---------------- pairwise projection; per-block inline transform composition ----------------
__global__ __launch_bounds__(256) void k_projpts(const float* __restrict__ points,
                                                 const float* __restrict__ depths,
                                                 const float* __restrict__ poses,
                                                 const float* __restrict__ Km) {
    __shared__ float sM[9], sV[3];
    int blk = blockIdx.x;                 // 144 blocks; each spans one (i,j), 256 n's
    int i = blk / 24;                     // 24 blocks per i
    int j = (blk % 24) >> 2;              // 4 blocks per j
    int nb = (blk & 3) * 256;
    int tid = threadIdx.x;

    if (tid == 0) {
        float a00=Km[0],a01=Km[1],a02=Km[2],a10=Km[3],a11=Km[4],a12=Km[5],a20=Km[6],a21=Km[7],a22=Km[8];
        float c00 = a11*a22-a12*a21, c01 = a02*a21-a01*a22, c02 = a01*a12-a02*a11;
        float c10 = a12*a20-a10*a22, c11 = a00*a22-a02*a20, c12 = a02*a10-a00*a12;
        float c20 = a10*a21-a11*a20, c21 = a01*a20-a00*a21, c22 = a00*a11-a01*a10;
        float det = a00*c00 + a01*c10 + a02*c20;
        float id = 1.0f/det;
        float KI[9] = { c00*id, c01*id, c02*id, c10*id, c11*id, c12*id, c20*id, c21*id, c22*id };
        float K[9]  = { a00,a01,a02, a10,a11,a12, a20,a21,a22 };
        const float* Pi = poses + i*16;
        const float* Pj = poses + j*16;
        float A[9], Bm[9];
        for (int r = 0; r < 3; r++)
            for (int cc = 0; cc < 3; cc++) {
                A[r*3+cc]  = Pi[cc*4+r];
                Bm[r*3+cc] = Pj[r*4+cc];
            }
        float T1[9], T2[9];
        for (int r = 0; r < 3; r++)
            for (int cc = 0; cc < 3; cc++)
                T1[r*3+cc] = K[r*3+0]*A[cc] + K[r*3+1]*A[3+cc] + K[r*3+2]*A[6+cc];
        for (int r = 0; r < 3; r++)
            for (int cc = 0; cc < 3; cc++)
                T2[r*3+cc] = T1[r*3+0]*Bm[cc] + T1[r*3+1]*Bm[3+cc] + T1[r*3+2]*Bm[6+cc];
        for (int r = 0; r < 3; r++)
            for (int cc = 0; cc < 3; cc++)
                sM[r*3+cc] = T2[r*3+0]*KI[cc] + T2[r*3+1]*KI[3+cc] + T2[r*3+2]*KI[6+cc];
        float dt[3] = { Pj[3]-Pi[3], Pj[7]-Pi[7], Pj[11]-Pi[11] };
        for (int r = 0; r < 3; r++)
            sV[r] = T1[r*3+0]*dt[0] + T1[r*3+1]*dt[1] + T1[r*3+2]*dt[2];
    }
    __syncthreads();

    int n = nb + tid;
    int t = (i*BB + j)*NN + n;
    float pnx = points[(j*NN+n)*2], pny = points[(j*NN+n)*2+1];
    float pxx = (pnx + 1.0f)*(float)(WW-1)*0.5f;
    float pxy = (pny + 1.0f)*(float)(HH-1)*0.5f;
    int xi = (int)fminf(fmaxf(rintf(pxx), 0.f), (float)(WW-1));
    int yi = (int)fminf(fmaxf(rintf(pxy), 0.f), (float)(HH-1));
    float dep = depths[(j*HH + yi)*WW + xi];
    float q0 = sM[0]*pxx + sM[1]*pxy + sM[2];
    float q1 = sM[3]*pxx + sM[4]*pxy + sM[5];
    float q2 = sM[6]*pxx + sM[7]*pxy + sM[8];
    float uu = fmaf(q0, dep, sV[0]);
    float vv = fmaf(q1, dep, sV[1]);
    float ww = fmaf(q2, dep, sV[2]);
    float z = ww;
    float zs = (fabsf(ww) > 1e-6f) ? ww : 1e-6f;
    float u = uu/zs, v = vv/zs;
    bool vis = (z > 0.1f) && (u >= 0.f) && (u <= (float)(WW-1)) && (v >= 0.f) && (v <= (float)(HH-1));
    float un = u*2.0f/(float)(WW-1) - 1.0f;
    float vn = v*2.0f/(float)(HH-1) - 1.0f;
    float dxp = (un + 1.0f)*(float)(WW-1)*0.5f;
    float dyp = (vn + 1.0f)*(float)(HH-1)*0.5f;
    d_nd[t] = make_float4(dxp, dyp, 0.5f - 0.5f*(dxp*dxp + dyp*dyp), 0.f);
    d_vis[t] = vis ? 1 : 0;
    unsigned contrib = vis ? (unsigned)(NN - 1 - n) : 0u;
    #pragma unroll
    for (int o = 16; o > 0; o >>= 1) contrib += __shfl_xor_sync(~0u, contrib, o);
    if ((threadIdx.x & 31) == 0 && contrib)
        atomicAdd(&d_z.cnt[1], (unsigned long long)contrib);
}

// ---------------- merged vsum (separable) + psum (spatial grid) ----------------
__global__ __launch_bounds__(256) void k_vp() {   // grid (BB*BB, 4)
    __shared__ float ws[8];
    int ab = blockIdx.x; int a = ab/BB, b = ab%BB;
    int idx = blockIdx.y*256 + threadIdx.x;

    float vloc = 0.f;
    if (d_vis[ab*NN + idx]) {
        const float4* da = (const float4*)(d_descn + ((size_t)a*NN+idx)*DD);
        const float4* ss = (const float4*)(d_S + ((size_t)b*NN+idx)*DD);
        float dot = 0.f;
        #pragma unroll 8
        for (int c = 0; c < 32; c++) {
            float4 x = da[c], y = ss[c];
            dot += x.x*y.x + x.y*y.y + x.z*y.z + x.w*y.w;
        }
        vloc = dot;
    }

    float psum = 0.f; unsigned pcnt = 0;
    {
        float4 nd = d_nd[ab*NN + idx];
        if (nd.x >= 13.f && nd.x <= 306.f && nd.y >= 13.f && nd.y <= 306.f) {
            int cx0 = max(0, (int)floorf((nd.x - 1.01f)*(1.f/16.f)));
            int cx1 = min(CELLS-1, (int)floorf((nd.x + 1.01f)*(1.f/16.f)));
            int cy0 = max(0, (int)floorf((nd.y - 1.01f)*(1.f/16.f)));
            int cy1 = min(CELLS-1, (int)floorf((nd.y + 1.01f)*(1.f/16.f)));
            for (int cy = cy0; cy <= cy1; cy++)
            for (int cx = cx0; cx <= cx1; cx++) {
                int c = cy*CELLS + cx;
                int s0 = d_cellstart[b][c], s1 = d_cellstart[b][c+1];
                for (int k = s0; k < s1; k++) {
                    int m = d_cellidx[b][k];
                    if (m >= idx || !d_vis[ab*NN + m]) continue;
                    float4 pt = d_pt[b*NN + m];
                    float tt = fmaf(pt.y, nd.y, nd.z - pt.z);
                    tt = fmaf(pt.x, nd.x, tt);
                    if (tt >= 0.f) {
                        const float4* dm  = (const float4*)(d_descn + ((size_t)a*NN+m)*DD);
                        const float4* dnn = (const float4*)(d_descn + ((size_t)b*NN+idx)*DD);
                        float dot = 0.f;
                        #pragma unroll 8
                        for (int c4 = 0; c4 < 32; c4++) {
                            float4 x = dm[c4], y = dnn[c4];
                            dot += x.x*y.x + x.y*y.y + x.z*y.z + x.w*y.w;
                        }
                        psum += dot; pcnt++;
                    }
                }
            }
        }
    }

    #pragma unroll
    for (int o = 16; o > 0; o >>= 1) {
        vloc += __shfl_xor_sync(~0u, vloc, o);
        psum += __shfl_xor_sync(~0u, psum, o);
        pcnt += __shfl_xor_sync(~0u, pcnt, o);
    }
    int lane = threadIdx.x & 31, w = threadIdx.x >> 5;
    if (lane == 0) {
        ws[w] = vloc;
        if (pcnt) {
            atomicAdd(&d_z.acc[1], (double)psum);
            atomicAdd(&d_z.cnt[0], (unsigned long long)pcnt);
        }
    }
    __syncthreads();
    if (w == 0) {
        float v = (lane < 8) ? ws[lane] : 0.f;
        #pragma unroll
        for (int o = 4; o > 0; o >>= 1) v += __shfl_xor_sync(~0u, v, o);
        if (lane == 0) atomicAdd(&d_z.acc[3], (double)v);
    }
}

// ---------------- diagonal-only FP8 GEMM for distinction (relu-sum) ----------------
__device__ __forceinline__ void ldsm4(unsigned &r0, unsigned &r1, unsigned &r2, unsigned &r3, unsigned addr) {
    asm volatile("ldmatrix.sync.aligned.m8n8.x4.shared.b16 {%0,%1,%2,%3}, [%4];"
                 : "=r"(r0), "=r"(r1), "=r"(r2), "=r"(r3) : "r"(addr));
}
__device__ __forceinline__ void mma8(float* c, const unsigned* a, const unsigned* b) {
    asm volatile("mma.sync.aligned.m16n8k32.row.col.f32.e4m3.e4m3.f32 "
                 "{%0,%1,%2,%3}, {%4,%5,%6,%7}, {%8,%9}, {%0,%1,%2,%3};"
                 : "+f"(c[0]), "+f"(c[1]), "+f"(c[2]), "+f"(c[3])
                 : "r"(a[0]), "r"(a[1]), "r"(a[2]), "r"(a[3]), "r"(b[0]), "r"(b[1]));
}
__device__ __forceinline__ unsigned sw8(int row, int chunk) {
    return (unsigned)(((row << 3) + (chunk ^ (row & 7))) << 4);
}

__global__ __launch_bounds__(256, 3) void k_mdiag(void) {
    int bx = blockIdx.x, by = blockIdx.y;
    if (bx < 2*by) return;
    int a = blockIdx.z;
    bool straddle = ((bx >> 1) == by);
    float dw = straddle ? 1.0f : 2.0f;

    extern __shared__ __align__(16) char dynsmem[];
    char* Asm = dynsmem;
    char* Bsm = dynsmem + 16384;
    __shared__ float wsum[8];

    int m0 = by * 128, n0 = bx * 64;
    int tid = threadIdx.x;
    int lane = tid & 31, warp = tid >> 5;
    int wm = warp >> 1, wn = warp & 1;

    const uint4* Ag = (const uint4*)(d_desc8 + (size_t)(a*NN + m0)*DD);
    const uint4* Bg = (const uint4*)(d_desc8 + (size_t)(a*NN + n0)*DD);
    #pragma unroll
    for (int it = 0; it < 4; it++) {
        int e = tid + it*256;
        int row = e >> 3, ch = e & 7;
        *(uint4*)(Asm + sw8(row, ch)) = Ag[row*8 + ch];
    }
    #pragma unroll
    for (int it = 0; it < 2; it++) {
        int e = tid + it*256;
        int row = e >> 3, ch = e & 7;
        *(uint4*)(Bsm + sw8(row, ch)) = Bg[row*8 + ch];
    }
    __syncthreads();

    unsigned Abase = (unsigned)__cvta_generic_to_shared(Asm);
    unsigned Bbase = (unsigned)__cvta_generic_to_shared(Bsm);

    float acc[2][4][4];
    #pragma unroll
    for (int mi = 0; mi < 2; mi++)
        #pragma unroll
        for (int ni = 0; ni < 4; ni++)
            #pragma unroll
            for (int c = 0; c < 4; c++) acc[mi][ni][c] = 0.f;

    #pragma unroll
    for (int ks = 0; ks < 4; ks++) {
        unsigned af[2][4];
        #pragma unroll
        for (int mi = 0; mi < 2; mi++) {
            int row = wm*32 + mi*16 + (lane & 15);
            int ch  = ks*2 + (lane >> 4);
            ldsm4(af[mi][0], af[mi][1], af[mi][2], af[mi][3], Abase + sw8(row, ch));
        }
        unsigned bf[4][2];
        #pragma unroll
        for (int g = 0; g < 2; g++) {
            int ni0 = g*2;
            int row = wn*32 + (ni0 + (lane >> 4))*8 + (lane & 7);
            int ch  = ks*2 + ((lane >> 3) & 1);
            ldsm4(bf[ni0][0], bf[ni0][1], bf[ni0+1][0], bf[ni0+1][1], Bbase + sw8(row, ch));
        }
        #pragma unroll
        for (int mi = 0; mi < 2; mi++)
            #pragma unroll
            for (int ni = 0; ni < 4; ni++)
                mma8(acc[mi][ni], af[mi], bf[ni]);
    }

    float dsum = 0.f;
    if (straddle) {
        #pragma unroll
        for (int ni = 0; ni < 4; ni++) {
            int nb = n0 + wn*32 + ni*8 + (lane & 3)*2;
            #pragma unroll
            for (int mi = 0; mi < 2; mi++) {
                #pragma unroll
                for (int c = 0; c < 4; c++) {
                    int m = m0 + wm*32 + mi*16 + (c >> 1)*8 + (lane >> 2);
                    int n = nb + (c & 1);
                    float rl = fmaxf(acc[mi][ni][c], 0.f);
                    float wgt = (m < n) ? 2.f : ((m == n) ? 1.f : 0.f);
                    dsum = fmaf(wgt, rl, dsum);
                }
            }
        }
    } else {
        #pragma unroll
        for (int ni = 0; ni < 4; ni++)
            #pragma unroll
            for (int mi = 0; mi < 2; mi++)
                #pragma unroll
                for (int c = 0; c < 4; c++)
                    dsum += fmaxf(acc[mi][ni][c], 0.f);
        dsum *= dw;
    }

    #pragma unroll
    for (int o = 16; o > 0; o >>= 1) dsum += __shfl_xor_sync(~0u, dsum, o);
    if (lane == 0) wsum[warp] = dsum;
    __syncthreads();
    if (warp == 0) {
        float v = (lane < 8) ? wsum[lane] : 0.f;
        #pragma unroll
        for (int o = 4; o > 0; o >>= 1) v += __shfl_xor_sync(~0u, v, o);
        if (lane == 0) atomicAdd(&d_z.acc[0], (double)v);
    }
}

// ---------------- finalize ----------------
__global__ void k_fin(float* out) {
    double distinction = d_z.acc[0] / ((double)BB*(double)NN*(double)NN);
    unsigned long long pc = d_z.cnt[0], tot = d_z.cnt[1];
    unsigned long long nc = (tot > pc) ? (tot - pc) : 0ULL;
    double pos_mean = d_z.acc[1] / (double)(pc ? pc : 1ULL);
    double neg_mean = (d_z.acc[3] - d_z.acc[1]) / (double)(nc ? nc : 1ULL);
    double match = 1.0 - pos_mean + neg_mean;
    double bce = d_z.acc[5] / (double)BNP;
    double reg = d_z.acc[6] / (double)BNP * 10.0;
    out[0] = (float)(distinction + 0.5*(bce + reg) + match);
}

// ---------------- launch ----------------
extern "C" void kernel_launch(void* const* d_in, const int* in_sizes, int n_in,
                              void* d_out, int out_size) {
    const float* desc   = (const float*)d_in[0];
    const float* points = (const float*)d_in[1];
    const float* scores = (const float*)d_in[2];
    const float* depths = (const float*)d_in[3];
    const float* poses  = (const float*)d_in[4];
    const float* Km     = (const float*)d_in[5];
    const float* imgs   = (const float*)d_in[6];
    float* out = (float*)d_out;

    static cudaStream_t s2 = nullptr, s3 = nullptr;
    static cudaEvent_t evFork = nullptr, evPrep = nullptr, evProj = nullptr, evJoin = nullptr, evJoin3 = nullptr;
    static void* z_addr = nullptr;
    if (!s2) {
        cudaStreamCreateWithFlags(&s2, cudaStreamNonBlocking);
        cudaStreamCreateWithFlags(&s3, cudaStreamNonBlocking);
        cudaEventCreateWithFlags(&evFork, cudaEventDisableTiming);
        cudaEventCreateWithFlags(&evPrep, cudaEventDisableTiming);
        cudaEventCreateWithFlags(&evProj, cudaEventDisableTiming);
        cudaEventCreateWithFlags(&evJoin, cudaEventDisableTiming);
        cudaEventCreateWithFlags(&evJoin3, cudaEventDisableTiming);
        cudaFuncSetAttribute(k_mdiag, cudaFuncAttributeMaxDynamicSharedMemorySize, 24576);
        cudaFuncSetAttribute(k_front, cudaFuncAttributeMaxDynamicSharedMemorySize, 47104);
        cudaGetSymbolAddress(&z_addr, d_z);
    }

    cudaMemsetAsync(z_addr, 0, sizeof(ZeroBlob), 0);
    cudaEventRecord(evFork, 0);

    // s3: projection chain (no deps besides zero-blob) then diag GEMM after prep
    cudaStreamWaitEvent(s3, evFork, 0);
    k_projpts<<<144, 256, 0, s3>>>(points, depths, poses, Km);
    cudaEventRecord(evProj, s3);

    // s2: prep -> scan(+cells) -> vp
    cudaStreamWaitEvent(s2, evFork, 0);
    k_prep<<<(BB*NN + 255)/256, 256, 0, s2>>>(points, desc);
    cudaEventRecord(evPrep, s2);
    k_scan<<<dim3(BB, 4), 1024, 0, s2>>>();
    cudaStreamWaitEvent(s2, evProj, 0);
    k_vp<<<dim3(BB*BB, 4), 256, 0, s2>>>();
    cudaEventRecord(evJoin, s2);

    // s3 continues: mdiag after prep
    cudaStreamWaitEvent(s3, evPrep, 0);
    k_mdiag<<<dim3(16, 8, BB), 256, 24576, s3>>>();
    cudaEventRecord(evJoin3, s3);

    // image chain on default stream
    k_front<<<dim3(10, 10, BB), 512, 47104>>>(imgs);
    k_sort<<<BB, 1024>>>();
    k_scatter<<<(BB*BB*NCR + 255)/256, 256>>>(depths, poses, Km);
    k_score<<<dim3(10, 10, BB), 512>>>(scores);

    // join
    cudaStreamWaitEvent(0, evJoin, 0);
    cudaStreamWaitEvent(0, evJoin3, 0);
    k_fin<<<1, 1>>>(out);
}